// round 1
// baseline (speedup 1.0000x reference)
#include <cuda_runtime.h>
#include <math.h>

// Problem constants (fixed by dataset): B=1, N=384, C=H=128
#define NN   384
#define CC   128
#define MTOT (NN*NN)          // 147456 rows
#define EPS  1e-5f

// ---------------- scratch (static __device__ arrays; allocation-free) --------
// All big intermediates stored channel-major [H][M] so producer writes and
// consumer reads are coalesced. 4 x 75.5 MB = 302 MB.
__device__ float g_left [(size_t)CC * MTOT];   // left_t[h][i*N+k]
__device__ float g_right[(size_t)CC * MTOT];   // right_t[h][k*N+j]
__device__ float g_gate [(size_t)CC * MTOT];   // gate_t[h][i*N+j]
__device__ float g_outm [(size_t)CC * MTOT];   // out_t[h][i*N+j]
__device__ float g_WlE[CC*CC];
__device__ float g_WrE[CC*CC];
__device__ float g_bLE[CC];
__device__ float g_bRE[CC];

// ---------------- prep: fold LN gamma/beta into projection weights ----------
// W_eff[k][n] = g[k]*W[k][n];  b_eff[n] = b[n] + sum_k beta[k]*W[k][n]
__global__ void prep_kernel(const float* __restrict__ W,
                            const float* __restrict__ ln_g,
                            const float* __restrict__ ln_b,
                            const float* __restrict__ b,
                            float* __restrict__ WE,
                            float* __restrict__ bE)
{
    int k = blockIdx.x;
    int n = threadIdx.x;
    WE[k*CC + n] = ln_g[k] * W[k*CC + n];
    if (k == 0) {
        float s = b[n];
        for (int kk = 0; kk < CC; kk++) s += ln_b[kk] * W[kk*CC + n];
        bE[n] = s;
    }
}

// ---------------- shared GEMM helpers (128x128 tile, 8x8 micro, 256 thr) ----
// A_s: 128 rows x 128 cols in smem, row stride 132. W: global [128][128].
// w_s: 16x128 k-chunk staging. acc: 8x8 per-thread micro-tile.
__device__ __forceinline__ void gemm128(const float* __restrict__ A_s,
                                        const float* __restrict__ Wg,
                                        float* __restrict__ w_s,
                                        float acc[8][8],
                                        int ty, int tx, int tid)
{
#pragma unroll
    for (int i = 0; i < 8; i++)
#pragma unroll
        for (int j = 0; j < 8; j++) acc[i][j] = 0.f;

    for (int k0 = 0; k0 < 128; k0 += 16) {
        __syncthreads();                       // prev consumers of w_s done
#pragma unroll
        for (int i = 0; i < 8; i++)            // 2048 floats / 256 thr
            w_s[tid + i*256] = Wg[k0*128 + tid + i*256];
        __syncthreads();
#pragma unroll
        for (int kk = 0; kk < 16; kk++) {
            float a[8];
#pragma unroll
            for (int i = 0; i < 8; i++) a[i] = A_s[(ty*8 + i)*132 + k0 + kk];
            float4 w0 = *reinterpret_cast<const float4*>(w_s + kk*128 + tx*8);
            float4 w1 = *reinterpret_cast<const float4*>(w_s + kk*128 + tx*8 + 4);
            float wv[8] = {w0.x, w0.y, w0.z, w0.w, w1.x, w1.y, w1.z, w1.w};
#pragma unroll
            for (int i = 0; i < 8; i++)
#pragma unroll
                for (int j = 0; j < 8; j++) acc[i][j] = fmaf(a[i], wv[j], acc[i][j]);
        }
    }
    __syncthreads();
}

// Transposed store: micro-tiles -> stage[n][r] (stride 129) -> coalesced
// global write to dst[h][M] channel-major.
__device__ __forceinline__ void store_T(const float acc[8][8],
                                        const float* __restrict__ bias,
                                        bool do_sigmoid,
                                        float* __restrict__ stage,
                                        float* __restrict__ dst,
                                        size_t R0, int ty, int tx, int tid)
{
#pragma unroll
    for (int j = 0; j < 8; j++) {
        float b = __ldg(bias + tx*8 + j);
#pragma unroll
        for (int i = 0; i < 8; i++) {
            float v = acc[i][j] + b;
            if (do_sigmoid) v = 1.0f / (1.0f + expf(-v));
            stage[(tx*8 + j)*129 + ty*8 + i] = v;
        }
    }
    __syncthreads();
    for (int idx = tid; idx < 128*128; idx += 256) {
        int n = idx >> 7, r = idx & 127;
        dst[(size_t)n * MTOT + R0 + r] = stage[n*129 + r];
    }
    __syncthreads();
}

// ---------------- kernel A: LN + 3 projections --------------------------------
// grid 1152 blocks x 128 rows. smem: p_s(raw), xh_s(normalized), stage, w chunk.
__global__ void __launch_bounds__(256)
kernelA(const float* __restrict__ pair,
        const float* __restrict__ Wg_w,
        const float* __restrict__ bg)
{
    extern __shared__ float sm[];
    float* p_s   = sm;                      // 128*132
    float* xh_s  = p_s  + 128*132;          // 128*132
    float* stage = xh_s + 128*132;          // 128*129
    float* w_s   = stage + 128*129;         // 16*128
    float* mu_s  = w_s + 16*128;            // 128
    float* rs_s  = mu_s + 128;              // 128

    const int tid = threadIdx.x;
    const int ty = tid >> 4, tx = tid & 15;
    const size_t R0 = (size_t)blockIdx.x * 128;

    // load pair tile (coalesced float4)
    for (int i = tid; i < 128*32; i += 256) {
        int r = i >> 5, c4 = i & 31;
        *reinterpret_cast<float4*>(p_s + r*132 + c4*4) =
            *reinterpret_cast<const float4*>(pair + (R0 + r)*CC + c4*4);
    }
    __syncthreads();

    // LN stats: one thread per row (conflict-free: stride 132 -> bank t*4+..,
    // 4-way at worst, negligible cost)
    if (tid < 128) {
        const float* row = p_s + tid*132;
        float s = 0.f;
#pragma unroll 4
        for (int k = 0; k < 128; k++) s += row[k];
        float mu = s * (1.f/128.f);
        float v = 0.f;
#pragma unroll 4
        for (int k = 0; k < 128; k++) { float d = row[k] - mu; v += d*d; }
        mu_s[tid] = mu;
        rs_s[tid] = rsqrtf(v * (1.f/128.f) + EPS);
    }
    __syncthreads();
    for (int i = tid; i < 128*128; i += 256) {
        int r = i >> 7, c = i & 127;
        xh_s[r*132 + c] = (p_s[r*132 + c] - mu_s[r]) * rs_s[r];
    }
    // (gemm128's leading __syncthreads covers xh_s visibility)

    float acc[8][8];
    gemm128(xh_s, g_WlE, w_s, acc, ty, tx, tid);
    store_T(acc, g_bLE, false, stage, g_left,  R0, ty, tx, tid);
    gemm128(xh_s, g_WrE, w_s, acc, ty, tx, tid);
    store_T(acc, g_bRE, false, stage, g_right, R0, ty, tx, tid);
    gemm128(p_s,  Wg_w,  w_s, acc, ty, tx, tid);
    store_T(acc, bg,    true,  stage, g_gate,  R0, ty, tx, tid);
}

// ---------------- kernel B: per-channel 384x384x384 GEMM ----------------------
// grid (3,3,128): (j-tile, i-tile, h). 128x128 tile, k-chunk 16.
__global__ void __launch_bounds__(256)
kernelB()
{
    __shared__ float a_s[128*20];   // 128 rows x 16 k, stride 20
    __shared__ float b_s[16*132];   // 16 k x 128 cols, stride 132

    const int tid = threadIdx.x;
    const int ty = tid >> 4, tx = tid & 15;
    const int I0 = blockIdx.y * 128, J0 = blockIdx.x * 128;
    const int h  = blockIdx.z;

    const float* __restrict__ A = g_left  + (size_t)h * MTOT;  // [i][k], ld=384
    const float* __restrict__ B = g_right + (size_t)h * MTOT;  // [k][j], ld=384

    float acc[8][8];
#pragma unroll
    for (int i = 0; i < 8; i++)
#pragma unroll
        for (int j = 0; j < 8; j++) acc[i][j] = 0.f;

    for (int k0 = 0; k0 < NN; k0 += 16) {
        // A chunk: 128 rows x 16 = 512 float4
#pragma unroll
        for (int t = 0; t < 2; t++) {
            int i = tid + t*256;
            int r = i >> 2, c4 = i & 3;
            *reinterpret_cast<float4*>(a_s + r*20 + c4*4) =
                *reinterpret_cast<const float4*>(A + (size_t)(I0 + r)*NN + k0 + c4*4);
        }
        // B chunk: 16 rows x 128 = 512 float4
#pragma unroll
        for (int t = 0; t < 2; t++) {
            int i = tid + t*256;
            int r = i >> 5, c4 = i & 31;
            *reinterpret_cast<float4*>(b_s + r*132 + c4*4) =
                *reinterpret_cast<const float4*>(B + (size_t)(k0 + r)*NN + J0 + c4*4);
        }
        __syncthreads();
#pragma unroll
        for (int kk = 0; kk < 16; kk++) {
            float a[8];
#pragma unroll
            for (int i = 0; i < 8; i++) a[i] = a_s[(ty*8 + i)*20 + kk];
            float4 w0 = *reinterpret_cast<const float4*>(b_s + kk*132 + tx*8);
            float4 w1 = *reinterpret_cast<const float4*>(b_s + kk*132 + tx*8 + 4);
            float wv[8] = {w0.x, w0.y, w0.z, w0.w, w1.x, w1.y, w1.z, w1.w};
#pragma unroll
            for (int i = 0; i < 8; i++)
#pragma unroll
                for (int j = 0; j < 8; j++) acc[i][j] = fmaf(a[i], wv[j], acc[i][j]);
        }
        __syncthreads();
    }

    float* __restrict__ Od = g_outm + (size_t)h * MTOT;
#pragma unroll
    for (int i = 0; i < 8; i++) {
        float4 o0 = make_float4(acc[i][0], acc[i][1], acc[i][2], acc[i][3]);
        float4 o1 = make_float4(acc[i][4], acc[i][5], acc[i][6], acc[i][7]);
        size_t base = (size_t)(I0 + ty*8 + i)*NN + J0 + tx*8;
        *reinterpret_cast<float4*>(Od + base)     = o0;
        *reinterpret_cast<float4*>(Od + base + 4) = o1;
    }
}

// ---------------- kernel C: gate*out @ Wo + bo + residual + LN ---------------
__global__ void __launch_bounds__(256)
kernelC(const float* __restrict__ pair,
        const float* __restrict__ Wo,
        const float* __restrict__ bo,
        const float* __restrict__ ng,
        const float* __restrict__ nb,
        float* __restrict__ out)
{
    extern __shared__ float sm[];
    float* v_s  = sm;                  // 128*129 : v[r][h] = out*gate
    float* y_s  = v_s + 128*129;       // 128*129 : y[r][c]
    float* w_s  = y_s + 128*129;       // 128*128 : Wo
    float* mu_s = w_s + 128*128;
    float* rs_s = mu_s + 128;

    const int tid = threadIdx.x;
    const int ty = tid >> 4, tx = tid & 15;
    const size_t IJ0 = (size_t)blockIdx.x * 128;

    for (int i = tid; i < 128*128; i += 256) w_s[i] = Wo[i];
    for (int i = tid; i < 128*128; i += 256) {
        int h = i >> 7, r = i & 127;
        size_t g = (size_t)h * MTOT + IJ0 + r;      // both coalesced in r
        v_s[r*129 + h] = g_outm[g] * g_gate[g];
    }
    __syncthreads();

    float acc[8][8];
#pragma unroll
    for (int i = 0; i < 8; i++)
#pragma unroll
        for (int j = 0; j < 8; j++) acc[i][j] = 0.f;

#pragma unroll 4
    for (int h = 0; h < 128; h++) {
        float a[8];
#pragma unroll
        for (int i = 0; i < 8; i++) a[i] = v_s[(ty*8 + i)*129 + h];
        float4 w0 = *reinterpret_cast<const float4*>(w_s + h*128 + tx*8);
        float4 w1 = *reinterpret_cast<const float4*>(w_s + h*128 + tx*8 + 4);
        float wv[8] = {w0.x, w0.y, w0.z, w0.w, w1.x, w1.y, w1.z, w1.w};
#pragma unroll
        for (int i = 0; i < 8; i++)
#pragma unroll
            for (int j = 0; j < 8; j++) acc[i][j] = fmaf(a[i], wv[j], acc[i][j]);
    }

    // y = acc + bo + pair (residual), staged to smem for the row LN
#pragma unroll
    for (int i = 0; i < 8; i++) {
        int r = ty*8 + i;
        float4 p0 = *reinterpret_cast<const float4*>(pair + (IJ0 + r)*CC + tx*8);
        float4 p1 = *reinterpret_cast<const float4*>(pair + (IJ0 + r)*CC + tx*8 + 4);
        float pv[8] = {p0.x, p0.y, p0.z, p0.w, p1.x, p1.y, p1.z, p1.w};
#pragma unroll
        for (int j = 0; j < 8; j++) {
            float z = acc[i][j] + __ldg(bo + tx*8 + j) + pv[j];
            y_s[r*129 + tx*8 + j] = z;
        }
    }
    __syncthreads();

    if (tid < 128) {
        const float* row = y_s + tid*129;
        float s = 0.f;
#pragma unroll 4
        for (int c = 0; c < 128; c++) s += row[c];
        float mu = s * (1.f/128.f);
        float v = 0.f;
#pragma unroll 4
        for (int c = 0; c < 128; c++) { float d = row[c] - mu; v += d*d; }
        mu_s[tid] = mu;
        rs_s[tid] = rsqrtf(v * (1.f/128.f) + EPS);
    }
    __syncthreads();

    for (int i = tid; i < 128*128; i += 256) {
        int r = i >> 7, c = i & 127;
        float z = y_s[r*129 + c];
        out[(IJ0 + r)*CC + c] = (z - mu_s[r]) * rs_s[r] * __ldg(ng + c) + __ldg(nb + c);
    }
}

// ---------------- launch ------------------------------------------------------
extern "C" void kernel_launch(void* const* d_in, const int* in_sizes, int n_in,
                              void* d_out, int out_size)
{
    const float* pair   = (const float*)d_in[0];
    const float* ln_l_g = (const float*)d_in[1];
    const float* ln_l_b = (const float*)d_in[2];
    const float* ln_r_g = (const float*)d_in[3];
    const float* ln_r_b = (const float*)d_in[4];
    const float* Wl     = (const float*)d_in[5];
    const float* bl     = (const float*)d_in[6];
    const float* Wr     = (const float*)d_in[7];
    const float* br     = (const float*)d_in[8];
    const float* Wg     = (const float*)d_in[9];
    const float* bg     = (const float*)d_in[10];
    const float* Wo     = (const float*)d_in[11];
    const float* bo     = (const float*)d_in[12];
    const float* n_g    = (const float*)d_in[13];
    const float* n_b    = (const float*)d_in[14];
    float* out = (float*)d_out;

    // resolve scratch symbol addresses once per call (host-side, capture-safe)
    static float *pWlE = nullptr, *pWrE, *pbLE, *pbRE;
    if (!pWlE) {
        cudaGetSymbolAddress((void**)&pWlE, g_WlE);
        cudaGetSymbolAddress((void**)&pWrE, g_WrE);
        cudaGetSymbolAddress((void**)&pbLE, g_bLE);
        cudaGetSymbolAddress((void**)&pbRE, g_bRE);
    }

    const size_t smemA = (size_t)(128*132*2 + 128*129 + 16*128 + 256) * sizeof(float);
    const size_t smemC = (size_t)(128*129*2 + 128*128 + 256) * sizeof(float);
    cudaFuncSetAttribute(kernelA, cudaFuncAttributeMaxDynamicSharedMemorySize, (int)smemA);
    cudaFuncSetAttribute(kernelC, cudaFuncAttributeMaxDynamicSharedMemorySize, (int)smemC);

    prep_kernel<<<CC, CC>>>(Wl, ln_l_g, ln_l_b, bl, pWlE, pbLE);
    prep_kernel<<<CC, CC>>>(Wr, ln_r_g, ln_r_b, br, pWrE, pbRE);

    kernelA<<<MTOT/128, 256, smemA>>>(pair, Wg, bg);
    kernelB<<<dim3(NN/128, NN/128, CC), 256>>>();
    kernelC<<<MTOT/128, 256, smemC>>>(pair, Wo, bo, n_g, n_b, out);
}

// round 3
// speedup vs baseline: 1.2792x; 1.2792x over previous
#include <cuda_runtime.h>
#include <cuda_bf16.h>
#include <math.h>

// Problem constants (fixed by dataset): B=1, N=384, C=H=128
#define NN   384
#define CC   128
#define MTOT (NN*NN)          // 147456 rows
#define EPS  1e-5f

// ---------------- scratch (static __device__ arrays; allocation-free) --------
// left/right stored as PACKED split-bf16: word = (bf16(hi)<<16) | bf16(lo),
// hi = bf16(x), lo = bf16(x - hi). Same bytes as fp32; 3-term HMMA
// (hi*hi + hi*lo + lo*hi) recovers fp32-class accuracy.
__device__ unsigned g_leftP [(size_t)CC * MTOT];   // [h][i][k]  (k contiguous)
__device__ unsigned g_rightP[(size_t)CC * MTOT];   // [h][k][j]  (j contiguous)
__device__ float    g_gate  [(size_t)CC * MTOT];   // [h][i*N+j]
__device__ float    g_outm  [(size_t)CC * MTOT];   // [h][i*N+j]
__device__ float g_WlE[CC*CC];
__device__ float g_WrE[CC*CC];
__device__ float g_bLE[CC];
__device__ float g_bRE[CC];

// ---------------- HMMA helpers (baseline PTX, no arch-specific features) -----
__device__ __forceinline__ unsigned smem_u32(const void* p) {
    return (unsigned)__cvta_generic_to_shared(p);
}
__device__ __forceinline__ void ldmx4(unsigned r[4], unsigned addr) {
    asm volatile("ldmatrix.sync.aligned.m8n8.x4.shared.b16 {%0,%1,%2,%3}, [%4];"
        : "=r"(r[0]), "=r"(r[1]), "=r"(r[2]), "=r"(r[3]) : "r"(addr));
}
__device__ __forceinline__ void ldmx4t(unsigned r[4], unsigned addr) {
    asm volatile("ldmatrix.sync.aligned.m8n8.x4.trans.shared.b16 {%0,%1,%2,%3}, [%4];"
        : "=r"(r[0]), "=r"(r[1]), "=r"(r[2]), "=r"(r[3]) : "r"(addr));
}
__device__ __forceinline__ void mma16816(float d[4], const unsigned a[4],
                                         unsigned b0, unsigned b1) {
    asm volatile(
        "mma.sync.aligned.m16n8k16.row.col.f32.bf16.bf16.f32 "
        "{%0,%1,%2,%3}, {%4,%5,%6,%7}, {%8,%9}, {%0,%1,%2,%3};"
        : "+f"(d[0]), "+f"(d[1]), "+f"(d[2]), "+f"(d[3])
        : "r"(a[0]), "r"(a[1]), "r"(a[2]), "r"(a[3]), "r"(b0), "r"(b1));
}

__device__ __forceinline__ unsigned pack_split(float v) {
    __nv_bfloat16 hi = __float2bfloat16(v);
    float r = v - __bfloat162float(hi);
    __nv_bfloat16 lo = __float2bfloat16(r);
    return ((unsigned)__bfloat16_as_ushort(hi) << 16) | (unsigned)__bfloat16_as_ushort(lo);
}

// ---------------- prep: fold LN gamma/beta into projection weights ----------
__global__ void prep_kernel(const float* __restrict__ W,
                            const float* __restrict__ ln_g,
                            const float* __restrict__ ln_b,
                            const float* __restrict__ b,
                            float* __restrict__ WE,
                            float* __restrict__ bE)
{
    int k = blockIdx.x;
    int n = threadIdx.x;
    WE[k*CC + n] = ln_g[k] * W[k*CC + n];
    if (k == 0) {
        float s = b[n];
        for (int kk = 0; kk < CC; kk++) s += ln_b[kk] * W[kk*CC + n];
        bE[n] = s;
    }
}

// ---------------- shared fp32 SIMT GEMM helper (kernelA/C) -------------------
__device__ __forceinline__ void gemm128(const float* __restrict__ A_s,
                                        const float* __restrict__ Wg,
                                        float* __restrict__ w_s,
                                        float acc[8][8],
                                        int ty, int tx, int tid)
{
#pragma unroll
    for (int i = 0; i < 8; i++)
#pragma unroll
        for (int j = 0; j < 8; j++) acc[i][j] = 0.f;

    for (int k0 = 0; k0 < 128; k0 += 16) {
        __syncthreads();
#pragma unroll
        for (int i = 0; i < 8; i++)
            w_s[tid + i*256] = Wg[k0*128 + tid + i*256];
        __syncthreads();
#pragma unroll
        for (int kk = 0; kk < 16; kk++) {
            float a[8];
#pragma unroll
            for (int i = 0; i < 8; i++) a[i] = A_s[(ty*8 + i)*132 + k0 + kk];
            float4 w0 = *reinterpret_cast<const float4*>(w_s + kk*128 + tx*8);
            float4 w1 = *reinterpret_cast<const float4*>(w_s + kk*128 + tx*8 + 4);
            float wv[8] = {w0.x, w0.y, w0.z, w0.w, w1.x, w1.y, w1.z, w1.w};
#pragma unroll
            for (int i = 0; i < 8; i++)
#pragma unroll
                for (int j = 0; j < 8; j++) acc[i][j] = fmaf(a[i], wv[j], acc[i][j]);
        }
    }
    __syncthreads();
}

// store split-bf16 packed, transposed to channel-major
__device__ __forceinline__ void store_T_pack(const float acc[8][8],
                                             const float* __restrict__ bias,
                                             unsigned* __restrict__ stage,
                                             unsigned* __restrict__ dst,
                                             size_t R0, int ty, int tx, int tid)
{
#pragma unroll
    for (int j = 0; j < 8; j++) {
        float b = __ldg(bias + tx*8 + j);
#pragma unroll
        for (int i = 0; i < 8; i++)
            stage[(tx*8 + j)*129 + ty*8 + i] = pack_split(acc[i][j] + b);
    }
    __syncthreads();
    for (int idx = tid; idx < 128*128; idx += 256) {
        int n = idx >> 7, r = idx & 127;
        dst[(size_t)n * MTOT + R0 + r] = stage[n*129 + r];
    }
    __syncthreads();
}

// store fp32 + sigmoid, transposed to channel-major (gate)
__device__ __forceinline__ void store_T_sig(const float acc[8][8],
                                            const float* __restrict__ bias,
                                            float* __restrict__ stage,
                                            float* __restrict__ dst,
                                            size_t R0, int ty, int tx, int tid)
{
#pragma unroll
    for (int j = 0; j < 8; j++) {
        float b = __ldg(bias + tx*8 + j);
#pragma unroll
        for (int i = 0; i < 8; i++) {
            float v = acc[i][j] + b;
            stage[(tx*8 + j)*129 + ty*8 + i] = 1.0f / (1.0f + expf(-v));
        }
    }
    __syncthreads();
    for (int idx = tid; idx < 128*128; idx += 256) {
        int n = idx >> 7, r = idx & 127;
        dst[(size_t)n * MTOT + R0 + r] = stage[n*129 + r];
    }
    __syncthreads();
}

// ---------------- kernel A: LN + 3 projections --------------------------------
__global__ void __launch_bounds__(256)
kernelA(const float* __restrict__ pair,
        const float* __restrict__ Wg_w,
        const float* __restrict__ bg)
{
    extern __shared__ float sm[];
    float* p_s   = sm;                      // 128*132
    float* xh_s  = p_s  + 128*132;          // 128*132
    float* stage = xh_s + 128*132;          // 128*129
    float* w_s   = stage + 128*129;         // 16*128
    float* mu_s  = w_s + 16*128;            // 128
    float* rs_s  = mu_s + 128;              // 128

    const int tid = threadIdx.x;
    const int ty = tid >> 4, tx = tid & 15;
    const size_t R0 = (size_t)blockIdx.x * 128;

    for (int i = tid; i < 128*32; i += 256) {
        int r = i >> 5, c4 = i & 31;
        *reinterpret_cast<float4*>(p_s + r*132 + c4*4) =
            *reinterpret_cast<const float4*>(pair + (R0 + r)*CC + c4*4);
    }
    __syncthreads();

    if (tid < 128) {
        const float* row = p_s + tid*132;
        float s = 0.f;
#pragma unroll 4
        for (int k = 0; k < 128; k++) s += row[k];
        float mu = s * (1.f/128.f);
        float v = 0.f;
#pragma unroll 4
        for (int k = 0; k < 128; k++) { float d = row[k] - mu; v += d*d; }
        mu_s[tid] = mu;
        rs_s[tid] = rsqrtf(v * (1.f/128.f) + EPS);
    }
    __syncthreads();
    for (int i = tid; i < 128*128; i += 256) {
        int r = i >> 7, c = i & 127;
        xh_s[r*132 + c] = (p_s[r*132 + c] - mu_s[r]) * rs_s[r];
    }

    float acc[8][8];
    gemm128(xh_s, g_WlE, w_s, acc, ty, tx, tid);
    store_T_pack(acc, g_bLE, (unsigned*)stage, g_leftP,  R0, ty, tx, tid);
    gemm128(xh_s, g_WrE, w_s, acc, ty, tx, tid);
    store_T_pack(acc, g_bRE, (unsigned*)stage, g_rightP, R0, ty, tx, tid);
    gemm128(p_s,  Wg_w,  w_s, acc, ty, tx, tid);
    store_T_sig(acc, bg, stage, g_gate, R0, ty, tx, tid);
}

// ---------------- kernel B: per-channel 384^3 GEMM on HMMA (mma.sync) --------
// D[i][j] = sum_k L[i][k] * R[k][j]; split-bf16 -> 3 accumulating MMAs.
// CTA tile 128x128, K-chunk 64, 8 warps, warp tile 32x64 (m16n8k16).
#define APAD 72     // A smem row stride (bf16 elems): 144B -> 4-bank row shift
#define BPAD 136    // B smem row stride: 272B -> 4-bank row shift

__global__ void __launch_bounds__(256, 1)
kernelB_mma()
{
    extern __shared__ __align__(16) __nv_bfloat16 smb[];
    __nv_bfloat16* aH = smb;                 // [128][APAD] rows = i, cols = k
    __nv_bfloat16* aL = aH + 128*APAD;
    __nv_bfloat16* bH = aL + 128*APAD;       // [64][BPAD]  rows = k, cols = j
    __nv_bfloat16* bL = bH + 64*BPAD;

    const int tid  = threadIdx.x;
    const int lane = tid & 31, wid = tid >> 5;
    const int J0 = blockIdx.x*128, I0 = blockIdx.y*128, h = blockIdx.z;
    const int wm = (wid & 3)*32;    // warp row offset in CTA tile
    const int wn = (wid >> 2)*64;   // warp col offset

    const unsigned* __restrict__ Ag = g_leftP  + (size_t)h*MTOT + (size_t)I0*NN;
    const unsigned* __restrict__ Bg = g_rightP + (size_t)h*MTOT;   // [k][j]

    float acc[2][8][4];
#pragma unroll
    for (int mi = 0; mi < 2; mi++)
#pragma unroll
        for (int nj = 0; nj < 8; nj++)
#pragma unroll
            for (int q = 0; q < 4; q++) acc[mi][nj][q] = 0.f;

    // ldmatrix lane-address components
    const int a_row = (lane & 7) + ((lane >> 3) & 1)*8;  // + wm + mi*16
    const int a_kh  = (lane >> 4)*8;                     // + kk
    const int b_kr  = (lane & 7) + ((lane >> 3) & 1)*8;  // + kk
    const int b_nc  = (lane >> 4)*8;                     // + wn + nh*16

    for (int k0 = 0; k0 < NN; k0 += 64) {
        __syncthreads();   // previous iteration's consumers done
#pragma unroll
        for (int t = 0; t < 8; t++) {
            int idx = tid + t*256;          // 0..2047
            {   // A: 128 rows x 16 uint4 (64 k)
                int r = idx >> 4, c4 = idx & 15;
                uint4 w = *reinterpret_cast<const uint4*>(Ag + (size_t)r*NN + k0 + c4*4);
                unsigned h0 = (w.x >> 16) | (w.y & 0xFFFF0000u);
                unsigned h1 = (w.z >> 16) | (w.w & 0xFFFF0000u);
                unsigned l0 = (w.x & 0xFFFFu) | (w.y << 16);
                unsigned l1 = (w.z & 0xFFFFu) | (w.w << 16);
                *reinterpret_cast<uint2*>(aH + r*APAD + c4*4) = make_uint2(h0, h1);
                *reinterpret_cast<uint2*>(aL + r*APAD + c4*4) = make_uint2(l0, l1);
            }
            {   // B: 64 rows x 32 uint4 (128 j)
                int r = idx >> 5, c4 = idx & 31;
                uint4 v = *reinterpret_cast<const uint4*>(Bg + (size_t)(k0 + r)*NN + J0 + c4*4);
                unsigned h0 = (v.x >> 16) | (v.y & 0xFFFF0000u);
                unsigned h1 = (v.z >> 16) | (v.w & 0xFFFF0000u);
                unsigned l0 = (v.x & 0xFFFFu) | (v.y << 16);
                unsigned l1 = (v.z & 0xFFFFu) | (v.w << 16);
                *reinterpret_cast<uint2*>(bH + r*BPAD + c4*4) = make_uint2(h0, h1);
                *reinterpret_cast<uint2*>(bL + r*BPAD + c4*4) = make_uint2(l0, l1);
            }
        }
        __syncthreads();

#pragma unroll
        for (int kk = 0; kk < 64; kk += 16) {
            unsigned aHf[2][4], aLf[2][4];
#pragma unroll
            for (int mi = 0; mi < 2; mi++) {
                const __nv_bfloat16* pa = aH + (wm + mi*16 + a_row)*APAD + kk + a_kh;
                ldmx4(aHf[mi], smem_u32(pa));
                ldmx4(aLf[mi], smem_u32(pa + 128*APAD));   // same offset in aL
            }
#pragma unroll
            for (int nh = 0; nh < 4; nh++) {
                const __nv_bfloat16* pb = bH + (kk + b_kr)*BPAD + wn + nh*16 + b_nc;
                unsigned bHf[4], bLf[4];
                ldmx4t(bHf, smem_u32(pb));
                ldmx4t(bLf, smem_u32(pb + 64*BPAD));       // same offset in bL
#pragma unroll
                for (int sub = 0; sub < 2; sub++) {
                    int nj = nh*2 + sub;
#pragma unroll
                    for (int mi = 0; mi < 2; mi++) {
                        mma16816(acc[mi][nj], aHf[mi], bHf[sub*2], bHf[sub*2+1]);
                        mma16816(acc[mi][nj], aHf[mi], bLf[sub*2], bLf[sub*2+1]);
                        mma16816(acc[mi][nj], aLf[mi], bHf[sub*2], bHf[sub*2+1]);
                    }
                }
            }
        }
    }

    // epilogue: D fragment -> fp32 global (float2 per thread, 32B/4-lane group)
    float* __restrict__ Od = g_outm + (size_t)h*MTOT;
#pragma unroll
    for (int mi = 0; mi < 2; mi++) {
        int r0 = I0 + wm + mi*16 + (lane >> 2);
#pragma unroll
        for (int nj = 0; nj < 8; nj++) {
            int c = J0 + wn + nj*8 + (lane & 3)*2;
            *reinterpret_cast<float2*>(Od + (size_t)r0*NN + c) =
                make_float2(acc[mi][nj][0], acc[mi][nj][1]);
            *reinterpret_cast<float2*>(Od + (size_t)(r0+8)*NN + c) =
                make_float2(acc[mi][nj][2], acc[mi][nj][3]);
        }
    }
}

// ---------------- kernel C: gate*out @ Wo + bo + residual + LN ---------------
__global__ void __launch_bounds__(256)
kernelC(const float* __restrict__ pair,
        const float* __restrict__ Wo,
        const float* __restrict__ bo,
        const float* __restrict__ ng,
        const float* __restrict__ nb,
        float* __restrict__ out)
{
    extern __shared__ float sm[];
    float* v_s  = sm;                  // 128*129
    float* y_s  = v_s + 128*129;       // 128*129
    float* w_s  = y_s + 128*129;       // 128*128
    float* mu_s = w_s + 128*128;
    float* rs_s = mu_s + 128;

    const int tid = threadIdx.x;
    const int ty = tid >> 4, tx = tid & 15;
    const size_t IJ0 = (size_t)blockIdx.x * 128;

    for (int i = tid; i < 128*128; i += 256) w_s[i] = Wo[i];
    for (int i = tid; i < 128*128; i += 256) {
        int h = i >> 7, r = i & 127;
        size_t g = (size_t)h * MTOT + IJ0 + r;
        v_s[r*129 + h] = g_outm[g] * g_gate[g];
    }
    __syncthreads();

    float acc[8][8];
#pragma unroll
    for (int i = 0; i < 8; i++)
#pragma unroll
        for (int j = 0; j < 8; j++) acc[i][j] = 0.f;

#pragma unroll 4
    for (int h = 0; h < 128; h++) {
        float a[8];
#pragma unroll
        for (int i = 0; i < 8; i++) a[i] = v_s[(ty*8 + i)*129 + h];
        float4 w0 = *reinterpret_cast<const float4*>(w_s + h*128 + tx*8);
        float4 w1 = *reinterpret_cast<const float4*>(w_s + h*128 + tx*8 + 4);
        float wv[8] = {w0.x, w0.y, w0.z, w0.w, w1.x, w1.y, w1.z, w1.w};
#pragma unroll
        for (int i = 0; i < 8; i++)
#pragma unroll
            for (int j = 0; j < 8; j++) acc[i][j] = fmaf(a[i], wv[j], acc[i][j]);
    }

#pragma unroll
    for (int i = 0; i < 8; i++) {
        int r = ty*8 + i;
        float4 p0 = *reinterpret_cast<const float4*>(pair + (IJ0 + r)*CC + tx*8);
        float4 p1 = *reinterpret_cast<const float4*>(pair + (IJ0 + r)*CC + tx*8 + 4);
        float pv[8] = {p0.x, p0.y, p0.z, p0.w, p1.x, p1.y, p1.z, p1.w};
#pragma unroll
        for (int j = 0; j < 8; j++) {
            float z = acc[i][j] + __ldg(bo + tx*8 + j) + pv[j];
            y_s[r*129 + tx*8 + j] = z;
        }
    }
    __syncthreads();

    if (tid < 128) {
        const float* row = y_s + tid*129;
        float s = 0.f;
#pragma unroll 4
        for (int c = 0; c < 128; c++) s += row[c];
        float mu = s * (1.f/128.f);
        float v = 0.f;
#pragma unroll 4
        for (int c = 0; c < 128; c++) { float d = row[c] - mu; v += d*d; }
        mu_s[tid] = mu;
        rs_s[tid] = rsqrtf(v * (1.f/128.f) + EPS);
    }
    __syncthreads();

    for (int i = tid; i < 128*128; i += 256) {
        int r = i >> 7, c = i & 127;
        float z = y_s[r*129 + c];
        out[(IJ0 + r)*CC + c] = (z - mu_s[r]) * rs_s[r] * __ldg(ng + c) + __ldg(nb + c);
    }
}

// ---------------- launch ------------------------------------------------------
extern "C" void kernel_launch(void* const* d_in, const int* in_sizes, int n_in,
                              void* d_out, int out_size)
{
    const float* pair   = (const float*)d_in[0];
    const float* ln_l_g = (const float*)d_in[1];
    const float* ln_l_b = (const float*)d_in[2];
    const float* ln_r_g = (const float*)d_in[3];
    const float* ln_r_b = (const float*)d_in[4];
    const float* Wl     = (const float*)d_in[5];
    const float* bl     = (const float*)d_in[6];
    const float* Wr     = (const float*)d_in[7];
    const float* br     = (const float*)d_in[8];
    const float* Wg     = (const float*)d_in[9];
    const float* bg     = (const float*)d_in[10];
    const float* Wo     = (const float*)d_in[11];
    const float* bo     = (const float*)d_in[12];
    const float* n_g    = (const float*)d_in[13];
    const float* n_b    = (const float*)d_in[14];
    float* out = (float*)d_out;

    static float *pWlE = nullptr, *pWrE, *pbLE, *pbRE;
    if (!pWlE) {
        cudaGetSymbolAddress((void**)&pWlE, g_WlE);
        cudaGetSymbolAddress((void**)&pWrE, g_WrE);
        cudaGetSymbolAddress((void**)&pbLE, g_bLE);
        cudaGetSymbolAddress((void**)&pbRE, g_bRE);
    }

    const size_t smemA = (size_t)(128*132*2 + 128*129 + 16*128 + 256) * sizeof(float);
    const size_t smemC = (size_t)(128*129*2 + 128*128 + 256) * sizeof(float);
    const size_t smemB = (size_t)(2*128*APAD + 2*64*BPAD) * sizeof(__nv_bfloat16);
    cudaFuncSetAttribute(kernelA,     cudaFuncAttributeMaxDynamicSharedMemorySize, (int)smemA);
    cudaFuncSetAttribute(kernelC,     cudaFuncAttributeMaxDynamicSharedMemorySize, (int)smemC);
    cudaFuncSetAttribute(kernelB_mma, cudaFuncAttributeMaxDynamicSharedMemorySize, (int)smemB);

    prep_kernel<<<CC, CC>>>(Wl, ln_l_g, ln_l_b, bl, pWlE, pbLE);
    prep_kernel<<<CC, CC>>>(Wr, ln_r_g, ln_r_b, br, pWrE, pbRE);

    kernelA<<<MTOT/128, 256, smemA>>>(pair, Wg, bg);
    kernelB_mma<<<dim3(NN/128, NN/128, CC), 256, smemB>>>();
    kernelC<<<MTOT/128, 256, smemC>>>(pair, Wo, bo, n_g, n_b, out);
}

// round 4
// speedup vs baseline: 1.8109x; 1.4157x over previous
#include <cuda_runtime.h>
#include <cuda_bf16.h>
#include <math.h>

// Problem constants (fixed by dataset): B=1, N=384, C=H=128
#define NN   384
#define CC   128
#define MTOT (NN*NN)          // 147456 rows
#define EPS  1e-5f

// ---------------- scratch (static __device__ arrays; allocation-free) --------
// Packed split-bf16: word = lo16 = bf16(x) at even col, hi16 = next col OR
// (hi,lo) split per element: here element split word = (bf16(x)<<0)|(bf16(res)<<16)
// convention used: see pack_split (hi in HIGH 16 bits, lo in LOW 16) for the
// per-element packed tensors g_leftP/g_rightP consumed by kernelB.
__device__ unsigned g_leftP [(size_t)CC * MTOT];   // [h][i][k]
__device__ unsigned g_rightP[(size_t)CC * MTOT];   // [h][k][j]
__device__ float    g_gate  [(size_t)CC * MTOT];   // [h][i*N+j]
__device__ float    g_outm  [(size_t)CC * MTOT];   // [h][i*N+j]
__device__ unsigned g_WlP[CC*CC];   // packed split weights (LN-folded)
__device__ unsigned g_WrP[CC*CC];
__device__ unsigned g_WgP[CC*CC];
__device__ unsigned g_WoP[CC*CC];
__device__ float g_bLE[CC];
__device__ float g_bRE[CC];
__device__ float g_WgS[CC];         // colsum of Wg
__device__ float g_WoS[CC];         // (unused)

// ---------------- HMMA helpers (baseline PTX only) ---------------------------
__device__ __forceinline__ unsigned smem_u32(const void* p) {
    return (unsigned)__cvta_generic_to_shared(p);
}
__device__ __forceinline__ void ldmx4(unsigned r[4], unsigned addr) {
    asm volatile("ldmatrix.sync.aligned.m8n8.x4.shared.b16 {%0,%1,%2,%3}, [%4];"
        : "=r"(r[0]), "=r"(r[1]), "=r"(r[2]), "=r"(r[3]) : "r"(addr));
}
__device__ __forceinline__ void ldmx4t(unsigned r[4], unsigned addr) {
    asm volatile("ldmatrix.sync.aligned.m8n8.x4.trans.shared.b16 {%0,%1,%2,%3}, [%4];"
        : "=r"(r[0]), "=r"(r[1]), "=r"(r[2]), "=r"(r[3]) : "r"(addr));
}
__device__ __forceinline__ void mma16816(float d[4], const unsigned a[4],
                                         unsigned b0, unsigned b1) {
    asm volatile(
        "mma.sync.aligned.m16n8k16.row.col.f32.bf16.bf16.f32 "
        "{%0,%1,%2,%3}, {%4,%5,%6,%7}, {%8,%9}, {%0,%1,%2,%3};"
        : "+f"(d[0]), "+f"(d[1]), "+f"(d[2]), "+f"(d[3])
        : "r"(a[0]), "r"(a[1]), "r"(a[2]), "r"(a[3]), "r"(b0), "r"(b1));
}
__device__ __forceinline__ unsigned pack_split(float v) {
    __nv_bfloat16 hi = __float2bfloat16(v);
    float r = v - __bfloat162float(hi);
    __nv_bfloat16 lo = __float2bfloat16(r);
    return ((unsigned)__bfloat16_as_ushort(hi) << 16) | (unsigned)__bfloat16_as_ushort(lo);
}
__device__ __forceinline__ void split2(float z0, float z1,
                                       unsigned& hw, unsigned& lw) {
    __nv_bfloat16 h0 = __float2bfloat16(z0);
    __nv_bfloat16 h1 = __float2bfloat16(z1);
    float r0 = z0 - __bfloat162float(h0);
    float r1 = z1 - __bfloat162float(h1);
    __nv_bfloat16 l0 = __float2bfloat16(r0);
    __nv_bfloat16 l1 = __float2bfloat16(r1);
    hw = (unsigned)__bfloat16_as_ushort(h0) | ((unsigned)__bfloat16_as_ushort(h1) << 16);
    lw = (unsigned)__bfloat16_as_ushort(l0) | ((unsigned)__bfloat16_as_ushort(l1) << 16);
}

// ---------------- prep kernels ------------------------------------------------
__global__ void prep_fold(const float* __restrict__ W,
                          const float* __restrict__ g,
                          const float* __restrict__ beta,
                          const float* __restrict__ b,
                          unsigned* __restrict__ WP,
                          float* __restrict__ bE)
{
    int k = blockIdx.x, n = threadIdx.x;
    WP[k*CC + n] = pack_split(g[k] * W[k*CC + n]);
    if (k == 0) {
        float s = b[n];
        for (int kk = 0; kk < CC; kk++) s += beta[kk] * W[kk*CC + n];
        bE[n] = s;
    }
}
__global__ void prep_pack(const float* __restrict__ W,
                          unsigned* __restrict__ WP,
                          float* __restrict__ S)
{
    int k = blockIdx.x, n = threadIdx.x;
    WP[k*CC + n] = pack_split(W[k*CC + n]);
    if (k == 0) {
        float s = 0.f;
        for (int kk = 0; kk < CC; kk++) s += W[kk*CC + n];
        S[n] = s;
    }
}

// ---------------- shared HMMA projection GEMM (128x128x128) ------------------
// A: split planes [128][XPAD] bf16 (row r, col k). W: packed global [128][128].
// acc: 2x8x4 fragments per thread. 8 warps: wm=(wid&3)*32, wn=(wid>>2)*64.
#define XPAD 136
#define BPAD 136
#define APAD 72

__device__ __forceinline__ void hmma_proj(
    const __nv_bfloat16* __restrict__ aHp,
    const __nv_bfloat16* __restrict__ aLp,
    const unsigned* __restrict__ Wp,
    __nv_bfloat16* __restrict__ bH, __nv_bfloat16* __restrict__ bL,
    float acc[2][8][4],
    int tid, int wm, int wn,
    int a_row, int a_kh, int b_kr, int b_nc)
{
#pragma unroll
    for (int mi = 0; mi < 2; mi++)
#pragma unroll
        for (int nj = 0; nj < 8; nj++)
#pragma unroll
            for (int q = 0; q < 4; q++) acc[mi][nj][q] = 0.f;

    for (int k0 = 0; k0 < 128; k0 += 64) {
        __syncthreads();
#pragma unroll
        for (int t = 0; t < 8; t++) {
            int idx = tid + t*256;
            int r = idx >> 5, c4 = idx & 31;
            uint4 v = *reinterpret_cast<const uint4*>(Wp + (k0 + r)*CC + c4*4);
            unsigned h0 = (v.x >> 16) | (v.y & 0xFFFF0000u);
            unsigned h1 = (v.z >> 16) | (v.w & 0xFFFF0000u);
            unsigned l0 = (v.x & 0xFFFFu) | (v.y << 16);
            unsigned l1 = (v.z & 0xFFFFu) | (v.w << 16);
            *reinterpret_cast<uint2*>(bH + r*BPAD + c4*4) = make_uint2(h0, h1);
            *reinterpret_cast<uint2*>(bL + r*BPAD + c4*4) = make_uint2(l0, l1);
        }
        __syncthreads();

#pragma unroll
        for (int kk = 0; kk < 64; kk += 16) {
            unsigned aHf[2][4], aLf[2][4];
#pragma unroll
            for (int mi = 0; mi < 2; mi++) {
                const __nv_bfloat16* pa = aHp + (wm + mi*16 + a_row)*XPAD + k0 + kk + a_kh;
                ldmx4(aHf[mi], smem_u32(pa));
                ldmx4(aLf[mi], smem_u32(aLp + (pa - aHp)));
            }
#pragma unroll
            for (int nh = 0; nh < 4; nh++) {
                const __nv_bfloat16* pb = bH + (kk + b_kr)*BPAD + wn + nh*16 + b_nc;
                unsigned bHf[4], bLf[4];
                ldmx4t(bHf, smem_u32(pb));
                ldmx4t(bLf, smem_u32(bL + (pb - bH)));
#pragma unroll
                for (int sub = 0; sub < 2; sub++) {
                    int nj = nh*2 + sub;
#pragma unroll
                    for (int mi = 0; mi < 2; mi++) {
                        mma16816(acc[mi][nj], aHf[mi], bHf[sub*2], bHf[sub*2+1]);
                        mma16816(acc[mi][nj], aHf[mi], bLf[sub*2], bLf[sub*2+1]);
                        mma16816(acc[mi][nj], aLf[mi], bHf[sub*2], bHf[sub*2+1]);
                    }
                }
            }
        }
    }
}

// fragment -> transposed channel-major global, split-bf16 packed
__device__ __forceinline__ void frag_store_pack(
    const float acc[2][8][4], const float* __restrict__ bias,
    unsigned* __restrict__ stage, unsigned* __restrict__ dst,
    size_t R0, int lane, int wm, int wn, int tid)
{
#pragma unroll
    for (int mi = 0; mi < 2; mi++) {
        int r = wm + mi*16 + (lane >> 2);
#pragma unroll
        for (int nj = 0; nj < 8; nj++) {
            int c = wn + nj*8 + (lane & 3)*2;
            float b0 = __ldg(bias + c), b1 = __ldg(bias + c + 1);
            stage[c*129 + r]       = pack_split(acc[mi][nj][0] + b0);
            stage[(c+1)*129 + r]   = pack_split(acc[mi][nj][1] + b1);
            stage[c*129 + r+8]     = pack_split(acc[mi][nj][2] + b0);
            stage[(c+1)*129 + r+8] = pack_split(acc[mi][nj][3] + b1);
        }
    }
    __syncthreads();
    for (int idx = tid; idx < 128*128; idx += 256) {
        int n = idx >> 7, r = idx & 127;
        dst[(size_t)n * MTOT + R0 + r] = stage[n*129 + r];
    }
    __syncthreads();
}

// gate: logit = sd[r]*acc + mu[r]*S[c] + bg[c]; sigmoid; fp32 channel-major
__device__ __forceinline__ void frag_store_gate(
    const float acc[2][8][4], const float* __restrict__ bg,
    const float* __restrict__ Sg,
    const float* __restrict__ sd_s, const float* __restrict__ mu_s,
    float* __restrict__ stage, float* __restrict__ dst,
    size_t R0, int lane, int wm, int wn, int tid)
{
#pragma unroll
    for (int mi = 0; mi < 2; mi++) {
        int r = wm + mi*16 + (lane >> 2);
        float sd0 = sd_s[r], mu0 = mu_s[r];
        float sd1 = sd_s[r+8], mu1 = mu_s[r+8];
#pragma unroll
        for (int nj = 0; nj < 8; nj++) {
            int c = wn + nj*8 + (lane & 3)*2;
            float S0 = __ldg(Sg + c) , B0 = __ldg(bg + c);
            float S1 = __ldg(Sg + c+1), B1 = __ldg(bg + c+1);
            float z;
            z = sd0*acc[mi][nj][0] + mu0*S0 + B0; stage[c*129 + r]       = 1.f/(1.f+expf(-z));
            z = sd0*acc[mi][nj][1] + mu0*S1 + B1; stage[(c+1)*129 + r]   = 1.f/(1.f+expf(-z));
            z = sd1*acc[mi][nj][2] + mu1*S0 + B0; stage[c*129 + r+8]     = 1.f/(1.f+expf(-z));
            z = sd1*acc[mi][nj][3] + mu1*S1 + B1; stage[(c+1)*129 + r+8] = 1.f/(1.f+expf(-z));
        }
    }
    __syncthreads();
    for (int idx = tid; idx < 128*128; idx += 256) {
        int n = idx >> 7, r = idx & 127;
        dst[(size_t)n * MTOT + R0 + r] = stage[n*129 + r];
    }
    __syncthreads();
}

// ---------------- kernel A: LN + 3 projections (HMMA) ------------------------
__global__ void __launch_bounds__(256, 1)
kernelA(const float* __restrict__ pair,
        const float* __restrict__ bg)
{
    extern __shared__ __align__(16) char smA[];
    float* p_s = (float*)smA;                               // 128*132 f  (67584 B), aliased by stage
    __nv_bfloat16* xhH = (__nv_bfloat16*)(smA + 67584);     // [128][XPAD]
    __nv_bfloat16* xhL = xhH + 128*XPAD;
    __nv_bfloat16* bH  = xhL + 128*XPAD;                    // [64][BPAD]
    __nv_bfloat16* bL  = bH + 64*BPAD;
    float* mu_s = (float*)(bL + 64*BPAD);
    float* rs_s = mu_s + 128;
    float* sd_s = rs_s + 128;
    unsigned* stageU = (unsigned*)smA;                      // alias p_s
    float*    stageF = (float*)smA;

    const int tid = threadIdx.x;
    const int lane = tid & 31, wid = tid >> 5;
    const int wm = (wid & 3)*32, wn = (wid >> 2)*64;
    const int a_row = (lane & 7) + ((lane >> 3) & 1)*8;
    const int a_kh  = (lane >> 4)*8;
    const int b_kr  = (lane & 7) + ((lane >> 3) & 1)*8;
    const int b_nc  = (lane >> 4)*8;
    const size_t R0 = (size_t)blockIdx.x * 128;

    for (int i = tid; i < 128*32; i += 256) {
        int r = i >> 5, c4 = i & 31;
        *reinterpret_cast<float4*>(p_s + r*132 + c4*4) =
            *reinterpret_cast<const float4*>(pair + (R0 + r)*CC + c4*4);
    }
    __syncthreads();

    if (tid < 128) {
        const float* row = p_s + tid*132;
        float s = 0.f;
#pragma unroll 4
        for (int k = 0; k < 128; k++) s += row[k];
        float mu = s * (1.f/128.f);
        float v = 0.f;
#pragma unroll 4
        for (int k = 0; k < 128; k++) { float d = row[k] - mu; v += d*d; }
        mu_s[tid] = mu;
        float var = v * (1.f/128.f) + EPS;
        rs_s[tid] = rsqrtf(var);
        sd_s[tid] = sqrtf(var);
    }
    __syncthreads();

    // xhat -> split-bf16 planes (packed 2 cols per word; conflict-free)
    for (int i = tid; i < 128*64; i += 256) {
        int r = i >> 6, c2 = i & 63;
        float mu = mu_s[r], rs = rs_s[r];
        float z0 = (p_s[r*132 + 2*c2]     - mu) * rs;
        float z1 = (p_s[r*132 + 2*c2 + 1] - mu) * rs;
        unsigned hw, lw;
        split2(z0, z1, hw, lw);
        *reinterpret_cast<unsigned*>(xhH + r*XPAD + 2*c2) = hw;
        *reinterpret_cast<unsigned*>(xhL + r*XPAD + 2*c2) = lw;
    }
    // hmma_proj's leading __syncthreads covers plane visibility

    float acc[2][8][4];
    hmma_proj(xhH, xhL, g_WlP, bH, bL, acc, tid, wm, wn, a_row, a_kh, b_kr, b_nc);
    frag_store_pack(acc, g_bLE, stageU, g_leftP,  R0, lane, wm, wn, tid);
    hmma_proj(xhH, xhL, g_WrP, bH, bL, acc, tid, wm, wn, a_row, a_kh, b_kr, b_nc);
    frag_store_pack(acc, g_bRE, stageU, g_rightP, R0, lane, wm, wn, tid);
    hmma_proj(xhH, xhL, g_WgP, bH, bL, acc, tid, wm, wn, a_row, a_kh, b_kr, b_nc);
    frag_store_gate(acc, bg, g_WgS, sd_s, mu_s, stageF, g_gate, R0, lane, wm, wn, tid);
}

// ---------------- kernel B: per-channel 384^3 GEMM (HMMA) — unchanged --------
__global__ void __launch_bounds__(256, 1)
kernelB_mma()
{
    extern __shared__ __align__(16) __nv_bfloat16 smb[];
    __nv_bfloat16* aH = smb;
    __nv_bfloat16* aL = aH + 128*APAD;
    __nv_bfloat16* bH = aL + 128*APAD;
    __nv_bfloat16* bL = bH + 64*BPAD;

    const int tid  = threadIdx.x;
    const int lane = tid & 31, wid = tid >> 5;
    const int J0 = blockIdx.x*128, I0 = blockIdx.y*128, h = blockIdx.z;
    const int wm = (wid & 3)*32;
    const int wn = (wid >> 2)*64;

    const unsigned* __restrict__ Ag = g_leftP  + (size_t)h*MTOT + (size_t)I0*NN;
    const unsigned* __restrict__ Bg = g_rightP + (size_t)h*MTOT;

    float acc[2][8][4];
#pragma unroll
    for (int mi = 0; mi < 2; mi++)
#pragma unroll
        for (int nj = 0; nj < 8; nj++)
#pragma unroll
            for (int q = 0; q < 4; q++) acc[mi][nj][q] = 0.f;

    const int a_row = (lane & 7) + ((lane >> 3) & 1)*8;
    const int a_kh  = (lane >> 4)*8;
    const int b_kr  = (lane & 7) + ((lane >> 3) & 1)*8;
    const int b_nc  = (lane >> 4)*8;

    for (int k0 = 0; k0 < NN; k0 += 64) {
        __syncthreads();
#pragma unroll
        for (int t = 0; t < 8; t++) {
            int idx = tid + t*256;
            {
                int r = idx >> 4, c4 = idx & 15;
                uint4 w = *reinterpret_cast<const uint4*>(Ag + (size_t)r*NN + k0 + c4*4);
                unsigned h0 = (w.x >> 16) | (w.y & 0xFFFF0000u);
                unsigned h1 = (w.z >> 16) | (w.w & 0xFFFF0000u);
                unsigned l0 = (w.x & 0xFFFFu) | (w.y << 16);
                unsigned l1 = (w.z & 0xFFFFu) | (w.w << 16);
                *reinterpret_cast<uint2*>(aH + r*APAD + c4*4) = make_uint2(h0, h1);
                *reinterpret_cast<uint2*>(aL + r*APAD + c4*4) = make_uint2(l0, l1);
            }
            {
                int r = idx >> 5, c4 = idx & 31;
                uint4 v = *reinterpret_cast<const uint4*>(Bg + (size_t)(k0 + r)*NN + J0 + c4*4);
                unsigned h0 = (v.x >> 16) | (v.y & 0xFFFF0000u);
                unsigned h1 = (v.z >> 16) | (v.w & 0xFFFF0000u);
                unsigned l0 = (v.x & 0xFFFFu) | (v.y << 16);
                unsigned l1 = (v.z & 0xFFFFu) | (v.w << 16);
                *reinterpret_cast<uint2*>(bH + r*BPAD + c4*4) = make_uint2(h0, h1);
                *reinterpret_cast<uint2*>(bL + r*BPAD + c4*4) = make_uint2(l0, l1);
            }
        }
        __syncthreads();

#pragma unroll
        for (int kk = 0; kk < 64; kk += 16) {
            unsigned aHf[2][4], aLf[2][4];
#pragma unroll
            for (int mi = 0; mi < 2; mi++) {
                const __nv_bfloat16* pa = aH + (wm + mi*16 + a_row)*APAD + kk + a_kh;
                ldmx4(aHf[mi], smem_u32(pa));
                ldmx4(aLf[mi], smem_u32(pa + 128*APAD));
            }
#pragma unroll
            for (int nh = 0; nh < 4; nh++) {
                const __nv_bfloat16* pb = bH + (kk + b_kr)*BPAD + wn + nh*16 + b_nc;
                unsigned bHf[4], bLf[4];
                ldmx4t(bHf, smem_u32(pb));
                ldmx4t(bLf, smem_u32(pb + 64*BPAD));
#pragma unroll
                for (int sub = 0; sub < 2; sub++) {
                    int nj = nh*2 + sub;
#pragma unroll
                    for (int mi = 0; mi < 2; mi++) {
                        mma16816(acc[mi][nj], aHf[mi], bHf[sub*2], bHf[sub*2+1]);
                        mma16816(acc[mi][nj], aHf[mi], bLf[sub*2], bLf[sub*2+1]);
                        mma16816(acc[mi][nj], aLf[mi], bHf[sub*2], bHf[sub*2+1]);
                    }
                }
            }
        }
    }

    float* __restrict__ Od = g_outm + (size_t)h*MTOT;
#pragma unroll
    for (int mi = 0; mi < 2; mi++) {
        int r0 = I0 + wm + mi*16 + (lane >> 2);
#pragma unroll
        for (int nj = 0; nj < 8; nj++) {
            int c = J0 + wn + nj*8 + (lane & 3)*2;
            *reinterpret_cast<float2*>(Od + (size_t)r0*NN + c) =
                make_float2(acc[mi][nj][0], acc[mi][nj][1]);
            *reinterpret_cast<float2*>(Od + (size_t)(r0+8)*NN + c) =
                make_float2(acc[mi][nj][2], acc[mi][nj][3]);
        }
    }
}

// ---------------- kernel C: gate*out @ Wo + bo + residual + LN (HMMA) --------
__global__ void __launch_bounds__(256, 1)
kernelC(const float* __restrict__ pair,
        const float* __restrict__ bo,
        const float* __restrict__ ng,
        const float* __restrict__ nb,
        float* __restrict__ out)
{
    extern __shared__ __align__(16) char smC[];
    __nv_bfloat16* vH = (__nv_bfloat16*)smC;                // [128][XPAD]
    __nv_bfloat16* vL = vH + 128*XPAD;
    __nv_bfloat16* bH = vL + 128*XPAD;                      // [64][BPAD]
    __nv_bfloat16* bL = bH + 64*BPAD;
    float* y_s  = (float*)(bL + 64*BPAD);                   // [128][129]
    float* mu_s = y_s + 128*129;
    float* rs_s = mu_s + 128;

    const int tid = threadIdx.x;
    const int lane = tid & 31, wid = tid >> 5;
    const int wm = (wid & 3)*32, wn = (wid >> 2)*64;
    const int a_row = (lane & 7) + ((lane >> 3) & 1)*8;
    const int a_kh  = (lane >> 4)*8;
    const int b_kr  = (lane & 7) + ((lane >> 3) & 1)*8;
    const int b_nc  = (lane >> 4)*8;
    const size_t IJ0 = (size_t)blockIdx.x * 128;

    // phase 1: v = out*gate, coalesced global reads -> y_s temp (conflict-free)
    for (int i = tid; i < 128*128; i += 256) {
        int h = i >> 7, r = i & 127;
        size_t g = (size_t)h * MTOT + IJ0 + r;
        y_s[r*129 + h] = g_outm[g] * g_gate[g];
    }
    __syncthreads();
    // phase 2: split to bf16 planes (r-major, packed word writes)
    for (int i = tid; i < 128*64; i += 256) {
        int r = i >> 6, c2 = i & 63;
        float z0 = y_s[r*129 + 2*c2];
        float z1 = y_s[r*129 + 2*c2 + 1];
        unsigned hw, lw;
        split2(z0, z1, hw, lw);
        *reinterpret_cast<unsigned*>(vH + r*XPAD + 2*c2) = hw;
        *reinterpret_cast<unsigned*>(vL + r*XPAD + 2*c2) = lw;
    }

    float acc[2][8][4];
    hmma_proj(vH, vL, g_WoP, bH, bL, acc, tid, wm, wn, a_row, a_kh, b_kr, b_nc);

    // epilogue: y = acc + bo + pair residual -> y_s
#pragma unroll
    for (int mi = 0; mi < 2; mi++) {
        int r = wm + mi*16 + (lane >> 2);
#pragma unroll
        for (int nj = 0; nj < 8; nj++) {
            int c = wn + nj*8 + (lane & 3)*2;
            float b0 = __ldg(bo + c), b1 = __ldg(bo + c + 1);
            float2 p0 = *reinterpret_cast<const float2*>(pair + (IJ0 + r)*CC + c);
            float2 p1 = *reinterpret_cast<const float2*>(pair + (IJ0 + r + 8)*CC + c);
            y_s[r*129 + c]       = acc[mi][nj][0] + b0 + p0.x;
            y_s[r*129 + c+1]     = acc[mi][nj][1] + b1 + p0.y;
            y_s[(r+8)*129 + c]   = acc[mi][nj][2] + b0 + p1.x;
            y_s[(r+8)*129 + c+1] = acc[mi][nj][3] + b1 + p1.y;
        }
    }
    __syncthreads();

    if (tid < 128) {
        const float* row = y_s + tid*129;
        float s = 0.f;
#pragma unroll 4
        for (int c = 0; c < 128; c++) s += row[c];
        float mu = s * (1.f/128.f);
        float v = 0.f;
#pragma unroll 4
        for (int c = 0; c < 128; c++) { float d = row[c] - mu; v += d*d; }
        mu_s[tid] = mu;
        rs_s[tid] = rsqrtf(v * (1.f/128.f) + EPS);
    }
    __syncthreads();

    for (int i = tid; i < 128*128; i += 256) {
        int r = i >> 7, c = i & 127;
        float z = y_s[r*129 + c];
        out[(IJ0 + r)*CC + c] = (z - mu_s[r]) * rs_s[r] * __ldg(ng + c) + __ldg(nb + c);
    }
}

// ---------------- launch ------------------------------------------------------
extern "C" void kernel_launch(void* const* d_in, const int* in_sizes, int n_in,
                              void* d_out, int out_size)
{
    const float* pair   = (const float*)d_in[0];
    const float* ln_l_g = (const float*)d_in[1];
    const float* ln_l_b = (const float*)d_in[2];
    const float* ln_r_g = (const float*)d_in[3];
    const float* ln_r_b = (const float*)d_in[4];
    const float* Wl     = (const float*)d_in[5];
    const float* bl     = (const float*)d_in[6];
    const float* Wr     = (const float*)d_in[7];
    const float* br     = (const float*)d_in[8];
    const float* Wg     = (const float*)d_in[9];
    const float* bg     = (const float*)d_in[10];
    const float* Wo     = (const float*)d_in[11];
    const float* bo     = (const float*)d_in[12];
    const float* n_g    = (const float*)d_in[13];
    const float* n_b    = (const float*)d_in[14];
    float* out = (float*)d_out;

    static unsigned *pWlP = nullptr, *pWrP, *pWgP, *pWoP;
    static float *pbLE, *pbRE, *pWgS, *pWoS;
    if (!pWlP) {
        cudaGetSymbolAddress((void**)&pWlP, g_WlP);
        cudaGetSymbolAddress((void**)&pWrP, g_WrP);
        cudaGetSymbolAddress((void**)&pWgP, g_WgP);
        cudaGetSymbolAddress((void**)&pWoP, g_WoP);
        cudaGetSymbolAddress((void**)&pbLE, g_bLE);
        cudaGetSymbolAddress((void**)&pbRE, g_bRE);
        cudaGetSymbolAddress((void**)&pWgS, g_WgS);
        cudaGetSymbolAddress((void**)&pWoS, g_WoS);
    }

    const size_t smemA = 67584 + (size_t)2*128*XPAD*2 + (size_t)2*64*BPAD*2 + 3*512;
    const size_t smemC = (size_t)2*128*XPAD*2 + (size_t)2*64*BPAD*2 + 128*129*4 + 2*512;
    const size_t smemB = (size_t)(2*128*APAD + 2*64*BPAD) * sizeof(__nv_bfloat16);
    cudaFuncSetAttribute(kernelA,     cudaFuncAttributeMaxDynamicSharedMemorySize, (int)smemA);
    cudaFuncSetAttribute(kernelC,     cudaFuncAttributeMaxDynamicSharedMemorySize, (int)smemC);
    cudaFuncSetAttribute(kernelB_mma, cudaFuncAttributeMaxDynamicSharedMemorySize, (int)smemB);

    prep_fold<<<CC, CC>>>(Wl, ln_l_g, ln_l_b, bl, pWlP, pbLE);
    prep_fold<<<CC, CC>>>(Wr, ln_r_g, ln_r_b, br, pWrP, pbRE);
    prep_pack<<<CC, CC>>>(Wg, pWgP, pWgS);
    prep_pack<<<CC, CC>>>(Wo, pWoP, pWoS);

    kernelA<<<MTOT/128, 256, smemA>>>(pair, bg);
    kernelB_mma<<<dim3(NN/128, NN/128, CC), 256, smemB>>>();
    kernelC<<<MTOT/128, 256, smemC>>>(pair, bo, n_g, n_b, out);
}

// round 5
// speedup vs baseline: 1.8552x; 1.0244x over previous
#include <cuda_runtime.h>
#include <cuda_bf16.h>
#include <math.h>

// Problem constants (fixed by dataset): B=1, N=384, C=H=128
#define NN   384
#define CC   128
#define MTOT (NN*NN)          // 147456 rows
#define EPS  1e-5f
#define XPAD 136              // A-operand smem row stride (bf16)
#define BPAD 136              // B-operand smem row stride (bf16)
#define APAD 72               // kernelB A-tile smem row stride (bf16)

// ---------------- scratch (static __device__ arrays; allocation-free) --------
// Split-bf16 as SEPARATE planes: H = bf16(x), L = bf16(x - H).
// 3-term HMMA (H*H' + H*L' + L*H') recovers fp32-class accuracy.
__device__ __nv_bfloat16 g_leftH [(size_t)CC * MTOT];   // [h][i][k]
__device__ __nv_bfloat16 g_leftL [(size_t)CC * MTOT];
__device__ __nv_bfloat16 g_rightH[(size_t)CC * MTOT];   // [h][k][j]
__device__ __nv_bfloat16 g_rightL[(size_t)CC * MTOT];
__device__ float g_gate[(size_t)CC * MTOT];             // [h][i*N+j]
__device__ float g_outm[(size_t)CC * MTOT];             // [h][i*N+j]
__device__ __nv_bfloat16 g_WlH[CC*CC], g_WlL[CC*CC];    // LN-folded, [k][n]
__device__ __nv_bfloat16 g_WrH[CC*CC], g_WrL[CC*CC];
__device__ __nv_bfloat16 g_WgH[CC*CC], g_WgL[CC*CC];
__device__ __nv_bfloat16 g_WoH[CC*CC], g_WoL[CC*CC];
__device__ float g_bLE[CC], g_bRE[CC], g_WgS[CC];

// ---------------- helpers (baseline PTX only; no sm_103a-specific ops) -------
__device__ __forceinline__ unsigned smem_u32(const void* p) {
    return (unsigned)__cvta_generic_to_shared(p);
}
__device__ __forceinline__ void cp16(unsigned saddr, const void* g) {
    asm volatile("cp.async.cg.shared.global [%0], [%1], 16;" :: "r"(saddr), "l"(g));
}
__device__ __forceinline__ void cp_commit() {
    asm volatile("cp.async.commit_group;" ::: "memory");
}
template<int N>
__device__ __forceinline__ void cp_wait() {
    asm volatile("cp.async.wait_group %0;" :: "n"(N) : "memory");
}
__device__ __forceinline__ void ldmx4(unsigned r[4], unsigned addr) {
    asm volatile("ldmatrix.sync.aligned.m8n8.x4.shared.b16 {%0,%1,%2,%3}, [%4];"
        : "=r"(r[0]), "=r"(r[1]), "=r"(r[2]), "=r"(r[3]) : "r"(addr));
}
__device__ __forceinline__ void ldmx4t(unsigned r[4], unsigned addr) {
    asm volatile("ldmatrix.sync.aligned.m8n8.x4.trans.shared.b16 {%0,%1,%2,%3}, [%4];"
        : "=r"(r[0]), "=r"(r[1]), "=r"(r[2]), "=r"(r[3]) : "r"(addr));
}
__device__ __forceinline__ void mma16816(float d[4], const unsigned a[4],
                                         unsigned b0, unsigned b1) {
    asm volatile(
        "mma.sync.aligned.m16n8k16.row.col.f32.bf16.bf16.f32 "
        "{%0,%1,%2,%3}, {%4,%5,%6,%7}, {%8,%9}, {%0,%1,%2,%3};"
        : "+f"(d[0]), "+f"(d[1]), "+f"(d[2]), "+f"(d[3])
        : "r"(a[0]), "r"(a[1]), "r"(a[2]), "r"(a[3]), "r"(b0), "r"(b1));
}
__device__ __forceinline__ unsigned pack_split(float v) {   // hi<<16 | lo
    __nv_bfloat16 hi = __float2bfloat16(v);
    float r = v - __bfloat162float(hi);
    __nv_bfloat16 lo = __float2bfloat16(r);
    return ((unsigned)__bfloat16_as_ushort(hi) << 16) | (unsigned)__bfloat16_as_ushort(lo);
}
__device__ __forceinline__ void split2(float z0, float z1,
                                       unsigned& hw, unsigned& lw) {
    __nv_bfloat16 h0 = __float2bfloat16(z0);
    __nv_bfloat16 h1 = __float2bfloat16(z1);
    float r0 = z0 - __bfloat162float(h0);
    float r1 = z1 - __bfloat162float(h1);
    __nv_bfloat16 l0 = __float2bfloat16(r0);
    __nv_bfloat16 l1 = __float2bfloat16(r1);
    hw = (unsigned)__bfloat16_as_ushort(h0) | ((unsigned)__bfloat16_as_ushort(h1) << 16);
    lw = (unsigned)__bfloat16_as_ushort(l0) | ((unsigned)__bfloat16_as_ushort(l1) << 16);
}

// ---------------- prep kernels -----------------------------------------------
__global__ void prep_fold(const float* __restrict__ W,
                          const float* __restrict__ g,
                          const float* __restrict__ beta,
                          const float* __restrict__ b,
                          __nv_bfloat16* __restrict__ WH,
                          __nv_bfloat16* __restrict__ WL,
                          float* __restrict__ bE)
{
    int k = blockIdx.x, n = threadIdx.x;
    float v = g[k] * W[k*CC + n];
    __nv_bfloat16 hi = __float2bfloat16(v);
    WH[k*CC + n] = hi;
    WL[k*CC + n] = __float2bfloat16(v - __bfloat162float(hi));
    if (k == 0) {
        float s = b[n];
        for (int kk = 0; kk < CC; kk++) s += beta[kk] * W[kk*CC + n];
        bE[n] = s;
    }
}
__global__ void prep_pack(const float* __restrict__ W,
                          __nv_bfloat16* __restrict__ WH,
                          __nv_bfloat16* __restrict__ WL,
                          float* __restrict__ S)
{
    int k = blockIdx.x, n = threadIdx.x;
    float v = W[k*CC + n];
    __nv_bfloat16 hi = __float2bfloat16(v);
    WH[k*CC + n] = hi;
    WL[k*CC + n] = __float2bfloat16(v - __bfloat162float(hi));
    if (k == 0 && S) {
        float s = 0.f;
        for (int kk = 0; kk < CC; kk++) s += W[kk*CC + n];
        S[n] = s;
    }
}

// ---------------- HMMA projection GEMM (128x128x128, cp.async weights) -------
// A planes in smem [128][XPAD]; weights streamed from global H/L planes into a
// 2-stage smem ring (each stage: 2 planes x 64 x BPAD).
__device__ __forceinline__ void hmma_proj(
    const __nv_bfloat16* __restrict__ aHp,
    const __nv_bfloat16* __restrict__ aLp,
    const __nv_bfloat16* __restrict__ WH,
    const __nv_bfloat16* __restrict__ WL,
    __nv_bfloat16* __restrict__ wstage,
    float acc[2][8][4],
    int tid, int wm, int wn,
    int a_row, int a_kh, int b_kr, int b_nc)
{
    const int PLANE = 64*BPAD;
#pragma unroll
    for (int mi = 0; mi < 2; mi++)
#pragma unroll
        for (int nj = 0; nj < 8; nj++)
#pragma unroll
            for (int q = 0; q < 4; q++) acc[mi][nj][q] = 0.f;

    // prefetch both 64-k weight chunks (2 groups)
#pragma unroll
    for (int s = 0; s < 2; s++) {
        __nv_bfloat16* dH = wstage + s*2*PLANE;
        __nv_bfloat16* dL = dH + PLANE;
        int k0 = s*64;
#pragma unroll
        for (int t = 0; t < 8; t++) {
            int idx = tid + t*256;
            int r = idx >> 5, rem = idx & 31;
            int pl = rem >> 4, c = rem & 15;
            const __nv_bfloat16* src = (pl ? WL : WH) + (k0 + r)*CC + c*8;
            __nv_bfloat16* dst = (pl ? dL : dH) + r*BPAD + c*8;
            cp16(smem_u32(dst), src);
        }
        cp_commit();
    }

#pragma unroll
    for (int s = 0; s < 2; s++) {
        if (s == 0) cp_wait<1>(); else cp_wait<0>();
        __syncthreads();
        const __nv_bfloat16* bH = wstage + s*2*PLANE;
        const __nv_bfloat16* bL = bH + PLANE;
        int k0 = s*64;
#pragma unroll
        for (int kk = 0; kk < 64; kk += 16) {
            unsigned aHf[2][4], aLf[2][4];
#pragma unroll
            for (int mi = 0; mi < 2; mi++) {
                const __nv_bfloat16* pa = aHp + (wm + mi*16 + a_row)*XPAD + k0 + kk + a_kh;
                ldmx4(aHf[mi], smem_u32(pa));
                ldmx4(aLf[mi], smem_u32(aLp + (pa - aHp)));
            }
#pragma unroll
            for (int nh = 0; nh < 4; nh++) {
                const __nv_bfloat16* pb = bH + (kk + b_kr)*BPAD + wn + nh*16 + b_nc;
                unsigned bHf[4], bLf[4];
                ldmx4t(bHf, smem_u32(pb));
                ldmx4t(bLf, smem_u32(pb + PLANE));
#pragma unroll
                for (int sub = 0; sub < 2; sub++) {
                    int nj = nh*2 + sub;
#pragma unroll
                    for (int mi = 0; mi < 2; mi++) {
                        mma16816(acc[mi][nj], aHf[mi], bHf[sub*2], bHf[sub*2+1]);
                        mma16816(acc[mi][nj], aHf[mi], bLf[sub*2], bLf[sub*2+1]);
                        mma16816(acc[mi][nj], aLf[mi], bHf[sub*2], bHf[sub*2+1]);
                    }
                }
            }
        }
    }
    __syncthreads();   // protect wstage for the next call
}

// fragment -> transposed channel-major global, split into H/L bf16 planes
__device__ __forceinline__ void frag_store_pack(
    const float acc[2][8][4], const float* __restrict__ bias,
    unsigned* __restrict__ stage,
    __nv_bfloat16* __restrict__ dstH, __nv_bfloat16* __restrict__ dstL,
    size_t R0, int lane, int wm, int wn, int tid)
{
#pragma unroll
    for (int mi = 0; mi < 2; mi++) {
        int r = wm + mi*16 + (lane >> 2);
#pragma unroll
        for (int nj = 0; nj < 8; nj++) {
            int c = wn + nj*8 + (lane & 3)*2;
            float b0 = __ldg(bias + c), b1 = __ldg(bias + c + 1);
            stage[c*129 + r]       = pack_split(acc[mi][nj][0] + b0);
            stage[(c+1)*129 + r]   = pack_split(acc[mi][nj][1] + b1);
            stage[c*129 + r+8]     = pack_split(acc[mi][nj][2] + b0);
            stage[(c+1)*129 + r+8] = pack_split(acc[mi][nj][3] + b1);
        }
    }
    __syncthreads();
    for (int idx = tid; idx < 128*64; idx += 256) {
        int n = idx >> 6, r2 = idx & 63;
        unsigned w0 = stage[n*129 + 2*r2], w1 = stage[n*129 + 2*r2 + 1];
        unsigned hw = (w0 >> 16) | (w1 & 0xFFFF0000u);
        unsigned lw = (w0 & 0xFFFFu) | (w1 << 16);
        size_t base = (size_t)n*MTOT + R0 + 2*r2;
        *reinterpret_cast<unsigned*>(dstH + base) = hw;
        *reinterpret_cast<unsigned*>(dstL + base) = lw;
    }
    __syncthreads();
}

// gate: logit = sd[r]*acc + mu[r]*S[c] + bg[c]; sigmoid; fp32 channel-major
__device__ __forceinline__ void frag_store_gate(
    const float acc[2][8][4], const float* __restrict__ bg,
    const float* __restrict__ Sg,
    const float* __restrict__ sd_s, const float* __restrict__ mu_s,
    float* __restrict__ stage, float* __restrict__ dst,
    size_t R0, int lane, int wm, int wn, int tid)
{
#pragma unroll
    for (int mi = 0; mi < 2; mi++) {
        int r = wm + mi*16 + (lane >> 2);
        float sd0 = sd_s[r], mu0 = mu_s[r];
        float sd1 = sd_s[r+8], mu1 = mu_s[r+8];
#pragma unroll
        for (int nj = 0; nj < 8; nj++) {
            int c = wn + nj*8 + (lane & 3)*2;
            float S0 = __ldg(Sg + c) , B0 = __ldg(bg + c);
            float S1 = __ldg(Sg + c+1), B1 = __ldg(bg + c+1);
            float z;
            z = sd0*acc[mi][nj][0] + mu0*S0 + B0; stage[c*129 + r]       = 1.f/(1.f+expf(-z));
            z = sd0*acc[mi][nj][1] + mu0*S1 + B1; stage[(c+1)*129 + r]   = 1.f/(1.f+expf(-z));
            z = sd1*acc[mi][nj][2] + mu1*S0 + B0; stage[c*129 + r+8]     = 1.f/(1.f+expf(-z));
            z = sd1*acc[mi][nj][3] + mu1*S1 + B1; stage[(c+1)*129 + r+8] = 1.f/(1.f+expf(-z));
        }
    }
    __syncthreads();
    for (int idx = tid; idx < 128*128; idx += 256) {
        int n = idx >> 7, r = idx & 127;
        dst[(size_t)n * MTOT + R0 + r] = stage[n*129 + r];
    }
    __syncthreads();
}

// ---------------- kernel A: LN + 3 projections (HMMA, cp.async weights) ------
__global__ void __launch_bounds__(256, 1)
kernelA(const float* __restrict__ pair,
        const float* __restrict__ bg)
{
    extern __shared__ __align__(16) char smA[];
    float* p_s = (float*)smA;                               // 128*132 f (67584 B), aliased by stage
    __nv_bfloat16* xhH = (__nv_bfloat16*)(smA + 67584);     // [128][XPAD]
    __nv_bfloat16* xhL = xhH + 128*XPAD;
    __nv_bfloat16* wst = xhL + 128*XPAD;                    // 2 stages x 2 x 64*BPAD
    float* mu_s = (float*)(wst + 4*64*BPAD);
    float* rs_s = mu_s + 128;
    float* sd_s = rs_s + 128;
    unsigned* stageU = (unsigned*)smA;                      // alias p_s
    float*    stageF = (float*)smA;

    const int tid = threadIdx.x;
    const int lane = tid & 31, wid = tid >> 5;
    const int wm = (wid & 3)*32, wn = (wid >> 2)*64;
    const int a_row = (lane & 7) + ((lane >> 3) & 1)*8;
    const int a_kh  = (lane >> 4)*8;
    const int b_kr  = (lane & 7) + ((lane >> 3) & 1)*8;
    const int b_nc  = (lane >> 4)*8;
    const size_t R0 = (size_t)blockIdx.x * 128;

    for (int i = tid; i < 128*32; i += 256) {
        int r = i >> 5, c4 = i & 31;
        *reinterpret_cast<float4*>(p_s + r*132 + c4*4) =
            *reinterpret_cast<const float4*>(pair + (R0 + r)*CC + c4*4);
    }
    __syncthreads();

    if (tid < 128) {
        const float* row = p_s + tid*132;
        float s = 0.f;
#pragma unroll 4
        for (int k = 0; k < 128; k++) s += row[k];
        float mu = s * (1.f/128.f);
        float v = 0.f;
#pragma unroll 4
        for (int k = 0; k < 128; k++) { float d = row[k] - mu; v += d*d; }
        mu_s[tid] = mu;
        float var = v * (1.f/128.f) + EPS;
        rs_s[tid] = rsqrtf(var);
        sd_s[tid] = sqrtf(var);
    }
    __syncthreads();

    for (int i = tid; i < 128*64; i += 256) {
        int r = i >> 6, c2 = i & 63;
        float mu = mu_s[r], rs = rs_s[r];
        float z0 = (p_s[r*132 + 2*c2]     - mu) * rs;
        float z1 = (p_s[r*132 + 2*c2 + 1] - mu) * rs;
        unsigned hw, lw;
        split2(z0, z1, hw, lw);
        *reinterpret_cast<unsigned*>(xhH + r*XPAD + 2*c2) = hw;
        *reinterpret_cast<unsigned*>(xhL + r*XPAD + 2*c2) = lw;
    }
    // hmma_proj's internal __syncthreads covers plane visibility

    float acc[2][8][4];
    hmma_proj(xhH, xhL, g_WlH, g_WlL, wst, acc, tid, wm, wn, a_row, a_kh, b_kr, b_nc);
    frag_store_pack(acc, g_bLE, stageU, g_leftH, g_leftL, R0, lane, wm, wn, tid);
    hmma_proj(xhH, xhL, g_WrH, g_WrL, wst, acc, tid, wm, wn, a_row, a_kh, b_kr, b_nc);
    frag_store_pack(acc, g_bRE, stageU, g_rightH, g_rightL, R0, lane, wm, wn, tid);
    hmma_proj(xhH, xhL, g_WgH, g_WgL, wst, acc, tid, wm, wn, a_row, a_kh, b_kr, b_nc);
    frag_store_gate(acc, bg, g_WgS, sd_s, mu_s, stageF, g_gate, R0, lane, wm, wn, tid);
}

// ---------------- kernel B: per-channel 384^3 GEMM, 2-stage cp.async ---------
#define KB_STG (2*128*APAD + 2*64*BPAD)   // elements per stage

__device__ __forceinline__ void kb_prefetch(
    __nv_bfloat16* st,
    const __nv_bfloat16* __restrict__ AgH, const __nv_bfloat16* __restrict__ AgL,
    const __nv_bfloat16* __restrict__ BgH, const __nv_bfloat16* __restrict__ BgL,
    int k0, int tid)
{
    __nv_bfloat16* aH = st;
    __nv_bfloat16* aL = st + 128*APAD;
    __nv_bfloat16* bH = st + 2*128*APAD;
    __nv_bfloat16* bL = bH + 64*BPAD;
#pragma unroll
    for (int t = 0; t < 8; t++) {
        int idx = tid + t*256;
        int r = idx >> 4, rem = idx & 15;
        int pl = rem >> 3, c = rem & 7;
        const __nv_bfloat16* src = (pl ? AgL : AgH) + (size_t)r*NN + k0 + c*8;
        __nv_bfloat16* dst = (pl ? aL : aH) + r*APAD + c*8;
        cp16(smem_u32(dst), src);
    }
#pragma unroll
    for (int t = 0; t < 8; t++) {
        int idx = tid + t*256;
        int r = idx >> 5, rem = idx & 31;
        int pl = rem >> 4, c = rem & 15;
        const __nv_bfloat16* src = (pl ? BgL : BgH) + (size_t)(k0 + r)*NN + c*8;
        __nv_bfloat16* dst = (pl ? bL : bH) + r*BPAD + c*8;
        cp16(smem_u32(dst), src);
    }
}

__global__ void __launch_bounds__(256, 1)
kernelB_mma()
{
    extern __shared__ __align__(16) __nv_bfloat16 smb[];
    const int tid  = threadIdx.x;
    const int lane = tid & 31, wid = tid >> 5;
    const int J0 = blockIdx.x*128, I0 = blockIdx.y*128, h = blockIdx.z;
    const int wm = (wid & 3)*32, wn = (wid >> 2)*64;

    const __nv_bfloat16* __restrict__ AgH = g_leftH  + (size_t)h*MTOT + (size_t)I0*NN;
    const __nv_bfloat16* __restrict__ AgL = g_leftL  + (size_t)h*MTOT + (size_t)I0*NN;
    const __nv_bfloat16* __restrict__ BgH = g_rightH + (size_t)h*MTOT + J0;
    const __nv_bfloat16* __restrict__ BgL = g_rightL + (size_t)h*MTOT + J0;

    float acc[2][8][4];
#pragma unroll
    for (int mi = 0; mi < 2; mi++)
#pragma unroll
        for (int nj = 0; nj < 8; nj++)
#pragma unroll
            for (int q = 0; q < 4; q++) acc[mi][nj][q] = 0.f;

    const int a_row = (lane & 7) + ((lane >> 3) & 1)*8;
    const int a_kh  = (lane >> 4)*8;
    const int b_kr  = (lane & 7) + ((lane >> 3) & 1)*8;
    const int b_nc  = (lane >> 4)*8;

    kb_prefetch(smb, AgH, AgL, BgH, BgL, 0, tid);
    cp_commit();

    for (int ch = 0; ch < 6; ch++) {
        if (ch + 1 < 6) {
            kb_prefetch(smb + ((ch+1)&1)*KB_STG, AgH, AgL, BgH, BgL, (ch+1)*64, tid);
            cp_commit();
            cp_wait<1>();
        } else {
            cp_wait<0>();
        }
        __syncthreads();

        const __nv_bfloat16* aH = smb + (ch&1)*KB_STG;
        const __nv_bfloat16* bH = aH + 2*128*APAD;
#pragma unroll
        for (int kk = 0; kk < 64; kk += 16) {
            unsigned aHf[2][4], aLf[2][4];
#pragma unroll
            for (int mi = 0; mi < 2; mi++) {
                const __nv_bfloat16* pa = aH + (wm + mi*16 + a_row)*APAD + kk + a_kh;
                ldmx4(aHf[mi], smem_u32(pa));
                ldmx4(aLf[mi], smem_u32(pa + 128*APAD));
            }
#pragma unroll
            for (int nh = 0; nh < 4; nh++) {
                const __nv_bfloat16* pb = bH + (kk + b_kr)*BPAD + wn + nh*16 + b_nc;
                unsigned bHf[4], bLf[4];
                ldmx4t(bHf, smem_u32(pb));
                ldmx4t(bLf, smem_u32(pb + 64*BPAD));
#pragma unroll
                for (int sub = 0; sub < 2; sub++) {
                    int nj = nh*2 + sub;
#pragma unroll
                    for (int mi = 0; mi < 2; mi++) {
                        mma16816(acc[mi][nj], aHf[mi], bHf[sub*2], bHf[sub*2+1]);
                        mma16816(acc[mi][nj], aHf[mi], bLf[sub*2], bLf[sub*2+1]);
                        mma16816(acc[mi][nj], aLf[mi], bHf[sub*2], bHf[sub*2+1]);
                    }
                }
            }
        }
        __syncthreads();
    }

    float* __restrict__ Od = g_outm + (size_t)h*MTOT;
#pragma unroll
    for (int mi = 0; mi < 2; mi++) {
        int r0 = I0 + wm + mi*16 + (lane >> 2);
#pragma unroll
        for (int nj = 0; nj < 8; nj++) {
            int c = J0 + wn + nj*8 + (lane & 3)*2;
            *reinterpret_cast<float2*>(Od + (size_t)r0*NN + c) =
                make_float2(acc[mi][nj][0], acc[mi][nj][1]);
            *reinterpret_cast<float2*>(Od + (size_t)(r0+8)*NN + c) =
                make_float2(acc[mi][nj][2], acc[mi][nj][3]);
        }
    }
}

// ---------------- kernel C: gate*out @ Wo + bo + residual + LN (HMMA) --------
__global__ void __launch_bounds__(256, 1)
kernelC(const float* __restrict__ pair,
        const float* __restrict__ bo,
        const float* __restrict__ ng,
        const float* __restrict__ nb,
        float* __restrict__ out)
{
    extern __shared__ __align__(16) char smC[];
    __nv_bfloat16* vH = (__nv_bfloat16*)smC;                // [128][XPAD]
    __nv_bfloat16* vL = vH + 128*XPAD;
    __nv_bfloat16* wst = vL + 128*XPAD;                     // weight stages
    float* y_s  = (float*)(wst + 4*64*BPAD);                // [128][129]
    float* mu_s = y_s + 128*129;
    float* rs_s = mu_s + 128;

    const int tid = threadIdx.x;
    const int lane = tid & 31, wid = tid >> 5;
    const int wm = (wid & 3)*32, wn = (wid >> 2)*64;
    const int a_row = (lane & 7) + ((lane >> 3) & 1)*8;
    const int a_kh  = (lane >> 4)*8;
    const int b_kr  = (lane & 7) + ((lane >> 3) & 1)*8;
    const int b_nc  = (lane >> 4)*8;
    const size_t IJ0 = (size_t)blockIdx.x * 128;

    // phase 1: v = out*gate (coalesced channel-major reads) -> y_s staging
    for (int i = tid; i < 128*128; i += 256) {
        int h = i >> 7, r = i & 127;
        size_t g = (size_t)h * MTOT + IJ0 + r;
        y_s[r*129 + h] = g_outm[g] * g_gate[g];
    }
    __syncthreads();
    // phase 2: split to bf16 planes
    for (int i = tid; i < 128*64; i += 256) {
        int r = i >> 6, c2 = i & 63;
        float z0 = y_s[r*129 + 2*c2];
        float z1 = y_s[r*129 + 2*c2 + 1];
        unsigned hw, lw;
        split2(z0, z1, hw, lw);
        *reinterpret_cast<unsigned*>(vH + r*XPAD + 2*c2) = hw;
        *reinterpret_cast<unsigned*>(vL + r*XPAD + 2*c2) = lw;
    }

    float acc[2][8][4];
    hmma_proj(vH, vL, g_WoH, g_WoL, wst, acc, tid, wm, wn, a_row, a_kh, b_kr, b_nc);

    // epilogue: y = acc + bo + pair residual
#pragma unroll
    for (int mi = 0; mi < 2; mi++) {
        int r = wm + mi*16 + (lane >> 2);
#pragma unroll
        for (int nj = 0; nj < 8; nj++) {
            int c = wn + nj*8 + (lane & 3)*2;
            float b0 = __ldg(bo + c), b1 = __ldg(bo + c + 1);
            float2 p0 = *reinterpret_cast<const float2*>(pair + (IJ0 + r)*CC + c);
            float2 p1 = *reinterpret_cast<const float2*>(pair + (IJ0 + r + 8)*CC + c);
            y_s[r*129 + c]       = acc[mi][nj][0] + b0 + p0.x;
            y_s[r*129 + c+1]     = acc[mi][nj][1] + b1 + p0.y;
            y_s[(r+8)*129 + c]   = acc[mi][nj][2] + b0 + p1.x;
            y_s[(r+8)*129 + c+1] = acc[mi][nj][3] + b1 + p1.y;
        }
    }
    __syncthreads();

    if (tid < 128) {
        const float* row = y_s + tid*129;
        float s = 0.f;
#pragma unroll 4
        for (int c = 0; c < 128; c++) s += row[c];
        float mu = s * (1.f/128.f);
        float v = 0.f;
#pragma unroll 4
        for (int c = 0; c < 128; c++) { float d = row[c] - mu; v += d*d; }
        mu_s[tid] = mu;
        rs_s[tid] = rsqrtf(v * (1.f/128.f) + EPS);
    }
    __syncthreads();

    for (int i = tid; i < 128*128; i += 256) {
        int r = i >> 7, c = i & 127;
        float z = y_s[r*129 + c];
        out[(IJ0 + r)*CC + c] = (z - mu_s[r]) * rs_s[r] * __ldg(ng + c) + __ldg(nb + c);
    }
}

// ---------------- launch ------------------------------------------------------
extern "C" void kernel_launch(void* const* d_in, const int* in_sizes, int n_in,
                              void* d_out, int out_size)
{
    const float* pair   = (const float*)d_in[0];
    const float* ln_l_g = (const float*)d_in[1];
    const float* ln_l_b = (const float*)d_in[2];
    const float* ln_r_g = (const float*)d_in[3];
    const float* ln_r_b = (const float*)d_in[4];
    const float* Wl     = (const float*)d_in[5];
    const float* bl     = (const float*)d_in[6];
    const float* Wr     = (const float*)d_in[7];
    const float* br     = (const float*)d_in[8];
    const float* Wg     = (const float*)d_in[9];
    const float* bg     = (const float*)d_in[10];
    const float* Wo     = (const float*)d_in[11];
    const float* bo     = (const float*)d_in[12];
    const float* n_g    = (const float*)d_in[13];
    const float* n_b    = (const float*)d_in[14];
    float* out = (float*)d_out;

    static __nv_bfloat16 *pWlH = nullptr, *pWlL, *pWrH, *pWrL, *pWgH, *pWgL, *pWoH, *pWoL;
    static float *pbLE, *pbRE, *pWgS;
    if (!pWlH) {
        cudaGetSymbolAddress((void**)&pWlH, g_WlH);
        cudaGetSymbolAddress((void**)&pWlL, g_WlL);
        cudaGetSymbolAddress((void**)&pWrH, g_WrH);
        cudaGetSymbolAddress((void**)&pWrL, g_WrL);
        cudaGetSymbolAddress((void**)&pWgH, g_WgH);
        cudaGetSymbolAddress((void**)&pWgL, g_WgL);
        cudaGetSymbolAddress((void**)&pWoH, g_WoH);
        cudaGetSymbolAddress((void**)&pWoL, g_WoL);
        cudaGetSymbolAddress((void**)&pbLE, g_bLE);
        cudaGetSymbolAddress((void**)&pbRE, g_bRE);
        cudaGetSymbolAddress((void**)&pWgS, g_WgS);
    }

    const size_t smemA = 67584 + (size_t)2*128*XPAD*2 + (size_t)4*64*BPAD*2 + 3*512;
    const size_t smemC = (size_t)2*128*XPAD*2 + (size_t)4*64*BPAD*2 + 128*129*4 + 2*512;
    const size_t smemB = (size_t)2*KB_STG * sizeof(__nv_bfloat16);
    cudaFuncSetAttribute(kernelA,     cudaFuncAttributeMaxDynamicSharedMemorySize, (int)smemA);
    cudaFuncSetAttribute(kernelC,     cudaFuncAttributeMaxDynamicSharedMemorySize, (int)smemC);
    cudaFuncSetAttribute(kernelB_mma, cudaFuncAttributeMaxDynamicSharedMemorySize, (int)smemB);

    prep_fold<<<CC, CC>>>(Wl, ln_l_g, ln_l_b, bl, pWlH, pWlL, pbLE);
    prep_fold<<<CC, CC>>>(Wr, ln_r_g, ln_r_b, br, pWrH, pWrL, pbRE);
    prep_pack<<<CC, CC>>>(Wg, pWgH, pWgL, pWgS);
    prep_pack<<<CC, CC>>>(Wo, pWoH, pWoL, nullptr);

    kernelA<<<MTOT/128, 256, smemA>>>(pair, bg);
    kernelB_mma<<<dim3(NN/128, NN/128, CC), 256, smemB>>>();
    kernelC<<<MTOT/128, 256, smemC>>>(pair, bo, n_g, n_b, out);
}

// round 7
// speedup vs baseline: 2.1068x; 1.1356x over previous
#include <cuda_runtime.h>
#include <cuda_bf16.h>
#include <math.h>

// Problem constants (fixed by dataset): B=1, N=384, C=H=128
#define NN   384
#define CC   128
#define MTOT (NN*NN)
#define EPS  1e-5f
#define XPAD 136      // A-operand plane row stride (bf16)
#define BPAD 136      // B-operand / weight row stride (bf16)
#define APAD 72       // kernelB A-tile row stride (bf16)
#define T    512      // threads per block (16 warps)

// ---------------- scratch ------------------------------------------------------
__device__ __nv_bfloat16 g_leftH [(size_t)CC * MTOT];   // [h][i][k]
__device__ __nv_bfloat16 g_leftL [(size_t)CC * MTOT];
__device__ __nv_bfloat16 g_rightH[(size_t)CC * MTOT];   // [h][k][j]
__device__ __nv_bfloat16 g_rightL[(size_t)CC * MTOT];
__device__ float g_gate[(size_t)CC * MTOT];             // [h][i*N+j]
__device__ float g_outm[(size_t)CC * MTOT];             // [h][i*N+j]
__device__ __nv_bfloat16 g_WlH[CC*CC], g_WlL[CC*CC];
__device__ __nv_bfloat16 g_WrH[CC*CC], g_WrL[CC*CC];
__device__ __nv_bfloat16 g_WgH[CC*CC], g_WgL[CC*CC];
__device__ __nv_bfloat16 g_WoH[CC*CC], g_WoL[CC*CC];
__device__ float g_bLE[CC], g_bRE[CC], g_WgS[CC];

// ---------------- helpers (baseline PTX only) ----------------------------------
__device__ __forceinline__ unsigned smem_u32(const void* p) {
    return (unsigned)__cvta_generic_to_shared(p);
}
__device__ __forceinline__ void cp16(unsigned saddr, const void* g) {
    asm volatile("cp.async.cg.shared.global [%0], [%1], 16;" :: "r"(saddr), "l"(g));
}
__device__ __forceinline__ void cp_commit() {
    asm volatile("cp.async.commit_group;" ::: "memory");
}
template<int N>
__device__ __forceinline__ void cp_wait() {
    asm volatile("cp.async.wait_group %0;" :: "n"(N) : "memory");
}
__device__ __forceinline__ void ldmx4(unsigned r[4], unsigned addr) {
    asm volatile("ldmatrix.sync.aligned.m8n8.x4.shared.b16 {%0,%1,%2,%3}, [%4];"
        : "=r"(r[0]), "=r"(r[1]), "=r"(r[2]), "=r"(r[3]) : "r"(addr));
}
__device__ __forceinline__ void ldmx4t(unsigned r[4], unsigned addr) {
    asm volatile("ldmatrix.sync.aligned.m8n8.x4.trans.shared.b16 {%0,%1,%2,%3}, [%4];"
        : "=r"(r[0]), "=r"(r[1]), "=r"(r[2]), "=r"(r[3]) : "r"(addr));
}
__device__ __forceinline__ void mma16816(float d[4], const unsigned a[4],
                                         unsigned b0, unsigned b1) {
    asm volatile(
        "mma.sync.aligned.m16n8k16.row.col.f32.bf16.bf16.f32 "
        "{%0,%1,%2,%3}, {%4,%5,%6,%7}, {%8,%9}, {%0,%1,%2,%3};"
        : "+f"(d[0]), "+f"(d[1]), "+f"(d[2]), "+f"(d[3])
        : "r"(a[0]), "r"(a[1]), "r"(a[2]), "r"(a[3]), "r"(b0), "r"(b1));
}
__device__ __forceinline__ unsigned pack_split(float v) {   // hi<<16 | lo
    __nv_bfloat16 hi = __float2bfloat16(v);
    float r = v - __bfloat162float(hi);
    __nv_bfloat16 lo = __float2bfloat16(r);
    return ((unsigned)__bfloat16_as_ushort(hi) << 16) | (unsigned)__bfloat16_as_ushort(lo);
}
__device__ __forceinline__ void split2(float z0, float z1,
                                       unsigned& hw, unsigned& lw) {
    __nv_bfloat16 h0 = __float2bfloat16(z0);
    __nv_bfloat16 h1 = __float2bfloat16(z1);
    float r0 = z0 - __bfloat162float(h0);
    float r1 = z1 - __bfloat162float(h1);
    __nv_bfloat16 l0 = __float2bfloat16(r0);
    __nv_bfloat16 l1 = __float2bfloat16(r1);
    hw = (unsigned)__bfloat16_as_ushort(h0) | ((unsigned)__bfloat16_as_ushort(h1) << 16);
    lw = (unsigned)__bfloat16_as_ushort(l0) | ((unsigned)__bfloat16_as_ushort(l1) << 16);
}

// ---------------- prep kernels --------------------------------------------------
__global__ void prep_fold(const float* __restrict__ W,
                          const float* __restrict__ g,
                          const float* __restrict__ beta,
                          const float* __restrict__ b,
                          __nv_bfloat16* __restrict__ WH,
                          __nv_bfloat16* __restrict__ WL,
                          float* __restrict__ bE)
{
    int k = blockIdx.x, n = threadIdx.x;
    float v = g[k] * W[k*CC + n];
    __nv_bfloat16 hi = __float2bfloat16(v);
    WH[k*CC + n] = hi;
    WL[k*CC + n] = __float2bfloat16(v - __bfloat162float(hi));
    if (k == 0) {
        float s = b[n];
        for (int kk = 0; kk < CC; kk++) s += beta[kk] * W[kk*CC + n];
        bE[n] = s;
    }
}
__global__ void prep_pack(const float* __restrict__ W,
                          __nv_bfloat16* __restrict__ WH,
                          __nv_bfloat16* __restrict__ WL,
                          float* __restrict__ S)
{
    int k = blockIdx.x, n = threadIdx.x;
    float v = W[k*CC + n];
    __nv_bfloat16 hi = __float2bfloat16(v);
    WH[k*CC + n] = hi;
    WL[k*CC + n] = __float2bfloat16(v - __bfloat162float(hi));
    if (k == 0 && S) {
        float s = 0.f;
        for (int kk = 0; kk < CC; kk++) s += W[kk*CC + n];
        S[n] = s;
    }
}

// ---------------- HMMA projection GEMM (128x128x128, 16 warps, 16x64 tiles) ----
__device__ __forceinline__ void hmma_proj(
    const __nv_bfloat16* __restrict__ aHp,
    const __nv_bfloat16* __restrict__ aLp,
    const __nv_bfloat16* __restrict__ WH,
    const __nv_bfloat16* __restrict__ WL,
    __nv_bfloat16* __restrict__ wst,
    float acc[8][4],
    int tid, int wm, int wn,
    int a_row, int a_kh, int b_kr, int b_nc)
{
    const int PLANE = 64*BPAD;
#pragma unroll
    for (int nj = 0; nj < 8; nj++)
#pragma unroll
        for (int q = 0; q < 4; q++) acc[nj][q] = 0.f;

#pragma unroll
    for (int s = 0; s < 2; s++) {
        __nv_bfloat16* dH = wst + s*2*PLANE;
        __nv_bfloat16* dL = dH + PLANE;
        int k0 = s*64;
#pragma unroll
        for (int t = 0; t < 4; t++) {
            int idx = tid + t*T;            // 0..2047
            int r = idx >> 5, rem = idx & 31;
            int pl = rem >> 4, c = rem & 15;
            const __nv_bfloat16* src = (pl ? WL : WH) + (k0 + r)*CC + c*8;
            __nv_bfloat16* dst = (pl ? dL : dH) + r*BPAD + c*8;
            cp16(smem_u32(dst), src);
        }
        cp_commit();
    }

#pragma unroll
    for (int s = 0; s < 2; s++) {
        if (s == 0) cp_wait<1>(); else cp_wait<0>();
        __syncthreads();
        const __nv_bfloat16* bH = wst + s*2*PLANE;
        int k0 = s*64;
#pragma unroll
        for (int kk = 0; kk < 64; kk += 16) {
            unsigned aHf[4], aLf[4];
            const __nv_bfloat16* pa = aHp + (wm + a_row)*XPAD + k0 + kk + a_kh;
            ldmx4(aHf, smem_u32(pa));
            ldmx4(aLf, smem_u32(aLp + (pa - aHp)));
#pragma unroll
            for (int nh = 0; nh < 4; nh++) {
                const __nv_bfloat16* pb = bH + (kk + b_kr)*BPAD + wn + nh*16 + b_nc;
                unsigned bHf[4], bLf[4];
                ldmx4t(bHf, smem_u32(pb));
                ldmx4t(bLf, smem_u32(pb + PLANE));
#pragma unroll
                for (int sub = 0; sub < 2; sub++) {
                    int nj = nh*2 + sub;
                    mma16816(acc[nj], aHf, bHf[sub*2], bHf[sub*2+1]);
                    mma16816(acc[nj], aHf, bLf[sub*2], bLf[sub*2+1]);
                    mma16816(acc[nj], aLf, bHf[sub*2], bHf[sub*2+1]);
                }
            }
        }
    }
    __syncthreads();   // protect wst for next call
}

// fragment (16x64 tile) -> transposed channel-major global, split H/L planes
__device__ __forceinline__ void frag_store_pack(
    const float acc[8][4], const float* __restrict__ bias,
    unsigned* __restrict__ stage,
    __nv_bfloat16* __restrict__ dstH, __nv_bfloat16* __restrict__ dstL,
    size_t R0, int lane, int wm, int wn, int tid)
{
    int r = wm + (lane >> 2);
#pragma unroll
    for (int nj = 0; nj < 8; nj++) {
        int c = wn + nj*8 + (lane & 3)*2;
        float b0 = __ldg(bias + c), b1 = __ldg(bias + c + 1);
        stage[c*129 + r]       = pack_split(acc[nj][0] + b0);
        stage[(c+1)*129 + r]   = pack_split(acc[nj][1] + b1);
        stage[c*129 + r+8]     = pack_split(acc[nj][2] + b0);
        stage[(c+1)*129 + r+8] = pack_split(acc[nj][3] + b1);
    }
    __syncthreads();
    for (int idx = tid; idx < 128*64; idx += T) {
        int n = idx >> 6, r2 = idx & 63;
        unsigned w0 = stage[n*129 + 2*r2], w1 = stage[n*129 + 2*r2 + 1];
        unsigned hw = (w0 >> 16) | (w1 & 0xFFFF0000u);
        unsigned lw = (w0 & 0xFFFFu) | (w1 << 16);
        size_t base = (size_t)n*MTOT + R0 + 2*r2;
        *reinterpret_cast<unsigned*>(dstH + base) = hw;
        *reinterpret_cast<unsigned*>(dstL + base) = lw;
    }
    __syncthreads();
}

// gate: logit = sd[r]*acc + mu[r]*S[c] + bg[c]; sigmoid; fp32 channel-major
__device__ __forceinline__ void frag_store_gate(
    const float acc[8][4], const float* __restrict__ bg,
    const float* __restrict__ Sg,
    const float* __restrict__ sd_s, const float* __restrict__ mu_s,
    float* __restrict__ stage, float* __restrict__ dst,
    size_t R0, int lane, int wm, int wn, int tid)
{
    int r = wm + (lane >> 2);
    float sd0 = sd_s[r], mu0 = mu_s[r];
    float sd1 = sd_s[r+8], mu1 = mu_s[r+8];
#pragma unroll
    for (int nj = 0; nj < 8; nj++) {
        int c = wn + nj*8 + (lane & 3)*2;
        float S0 = __ldg(Sg + c) , B0 = __ldg(bg + c);
        float S1 = __ldg(Sg + c+1), B1 = __ldg(bg + c+1);
        float z;
        z = sd0*acc[nj][0] + mu0*S0 + B0; stage[c*129 + r]       = 1.f/(1.f+expf(-z));
        z = sd0*acc[nj][1] + mu0*S1 + B1; stage[(c+1)*129 + r]   = 1.f/(1.f+expf(-z));
        z = sd1*acc[nj][2] + mu1*S0 + B0; stage[c*129 + r+8]     = 1.f/(1.f+expf(-z));
        z = sd1*acc[nj][3] + mu1*S1 + B1; stage[(c+1)*129 + r+8] = 1.f/(1.f+expf(-z));
    }
    __syncthreads();
    for (int idx = tid; idx < 128*128; idx += T) {
        int n = idx >> 7, r2 = idx & 127;
        dst[(size_t)n * MTOT + R0 + r2] = stage[n*129 + r2];
    }
    __syncthreads();
}

// ---------------- kernel A: LN + 3 projections ---------------------------------
__global__ void __launch_bounds__(T, 1)
kernelA(const float* __restrict__ pair,
        const float* __restrict__ bg)
{
    extern __shared__ __align__(16) char smA[];
    __nv_bfloat16* xhH = (__nv_bfloat16*)smA;               // [128][XPAD]
    __nv_bfloat16* xhL = xhH + 128*XPAD;
    __nv_bfloat16* wst = xhL + 128*XPAD;                    // 2 stages x 2 planes x 64*BPAD
    char* stg = smA + 139264;                               // [128][129] u32/f32 stage
    unsigned* stageU = (unsigned*)stg;
    float*    stageF = (float*)stg;
    float* mu_s = (float*)(smA + 205312);
    float* rs_s = mu_s + 128;
    float* sd_s = rs_s + 128;

    const int tid = threadIdx.x;
    const int lane = tid & 31, wid = tid >> 5;
    const int wm = (wid & 7)*16, wn = (wid >> 3)*64;
    const int a_row = (lane & 7) + ((lane >> 3) & 1)*8;
    const int a_kh  = (lane >> 4)*8;
    const int b_kr  = (lane & 7) + ((lane >> 3) & 1)*8;
    const int b_nc  = (lane >> 4)*8;
    const size_t R0 = (size_t)blockIdx.x * 128;

    // LN stats: warp per 8 rows, coalesced global float4 read + shuffle reduce
#pragma unroll
    for (int rr = 0; rr < 8; rr++) {
        int r = wid*8 + rr;
        float4 v = *reinterpret_cast<const float4*>(pair + (R0 + r)*CC + lane*4);
        float s  = v.x + v.y + v.z + v.w;
        float s2 = v.x*v.x + v.y*v.y + v.z*v.z + v.w*v.w;
#pragma unroll
        for (int off = 16; off > 0; off >>= 1) {
            s  += __shfl_xor_sync(0xffffffffu, s,  off);
            s2 += __shfl_xor_sync(0xffffffffu, s2, off);
        }
        if (lane == 0) {
            float mu  = s * (1.f/128.f);
            float var = fmaxf(s2 * (1.f/128.f) - mu*mu, 0.f) + EPS;
            mu_s[r] = mu;
            rs_s[r] = rsqrtf(var);
            sd_s[r] = sqrtf(var);
        }
    }
    __syncthreads();

    // xhat -> split planes (pair re-read is L2-hot)
    for (int i = tid; i < 128*32; i += T) {
        int r = i >> 5, c4 = i & 31;
        float4 v = *reinterpret_cast<const float4*>(pair + (R0 + r)*CC + c4*4);
        float mu = mu_s[r], rs = rs_s[r];
        unsigned hw0, lw0, hw1, lw1;
        split2((v.x - mu)*rs, (v.y - mu)*rs, hw0, lw0);
        split2((v.z - mu)*rs, (v.w - mu)*rs, hw1, lw1);
        *reinterpret_cast<uint2*>(xhH + r*XPAD + c4*4) = make_uint2(hw0, hw1);
        *reinterpret_cast<uint2*>(xhL + r*XPAD + c4*4) = make_uint2(lw0, lw1);
    }
    // hmma_proj's internal sync (post cp_wait) orders plane writes before ldmatrix

    float acc[8][4];
    hmma_proj(xhH, xhL, g_WlH, g_WlL, wst, acc, tid, wm, wn, a_row, a_kh, b_kr, b_nc);
    frag_store_pack(acc, g_bLE, stageU, g_leftH, g_leftL, R0, lane, wm, wn, tid);
    hmma_proj(xhH, xhL, g_WrH, g_WrL, wst, acc, tid, wm, wn, a_row, a_kh, b_kr, b_nc);
    frag_store_pack(acc, g_bRE, stageU, g_rightH, g_rightL, R0, lane, wm, wn, tid);
    hmma_proj(xhH, xhL, g_WgH, g_WgL, wst, acc, tid, wm, wn, a_row, a_kh, b_kr, b_nc);
    frag_store_gate(acc, bg, g_WgS, sd_s, mu_s, stageF, g_gate, R0, lane, wm, wn, tid);
}

// ---------------- kernel B: per-channel 384^3 GEMM -----------------------------
#define KB_STG (2*128*APAD + 2*64*BPAD)   // bf16 elements per stage

__device__ __forceinline__ void kb_prefetch(
    __nv_bfloat16* st,
    const __nv_bfloat16* __restrict__ AgH, const __nv_bfloat16* __restrict__ AgL,
    const __nv_bfloat16* __restrict__ BgH, const __nv_bfloat16* __restrict__ BgL,
    int k0, int tid)
{
    __nv_bfloat16* aH = st;
    __nv_bfloat16* aL = st + 128*APAD;
    __nv_bfloat16* bH = st + 2*128*APAD;
    __nv_bfloat16* bL = bH + 64*BPAD;
#pragma unroll
    for (int t = 0; t < 4; t++) {
        int idx = tid + t*T;
        int r = idx >> 4, rem = idx & 15;
        int pl = rem >> 3, c = rem & 7;
        const __nv_bfloat16* src = (pl ? AgL : AgH) + (size_t)r*NN + k0 + c*8;
        __nv_bfloat16* dst = (pl ? aL : aH) + r*APAD + c*8;
        cp16(smem_u32(dst), src);
    }
#pragma unroll
    for (int t = 0; t < 4; t++) {
        int idx = tid + t*T;
        int r = idx >> 5, rem = idx & 31;
        int pl = rem >> 4, c = rem & 15;
        const __nv_bfloat16* src = (pl ? BgL : BgH) + (size_t)(k0 + r)*NN + c*8;
        __nv_bfloat16* dst = (pl ? bL : bH) + r*BPAD + c*8;
        cp16(smem_u32(dst), src);
    }
}

__global__ void __launch_bounds__(T, 1)
kernelB_mma()
{
    extern __shared__ __align__(16) __nv_bfloat16 smb[];
    const int tid  = threadIdx.x;
    const int lane = tid & 31, wid = tid >> 5;
    const int J0 = blockIdx.x*128, I0 = blockIdx.y*128, h = blockIdx.z;
    const int wm = (wid & 7)*16, wn = (wid >> 3)*64;

    const __nv_bfloat16* __restrict__ AgH = g_leftH  + (size_t)h*MTOT + (size_t)I0*NN;
    const __nv_bfloat16* __restrict__ AgL = g_leftL  + (size_t)h*MTOT + (size_t)I0*NN;
    const __nv_bfloat16* __restrict__ BgH = g_rightH + (size_t)h*MTOT + J0;
    const __nv_bfloat16* __restrict__ BgL = g_rightL + (size_t)h*MTOT + J0;

    float acc[8][4];
#pragma unroll
    for (int nj = 0; nj < 8; nj++)
#pragma unroll
        for (int q = 0; q < 4; q++) acc[nj][q] = 0.f;

    const int a_row = (lane & 7) + ((lane >> 3) & 1)*8;
    const int a_kh  = (lane >> 4)*8;
    const int b_kr  = (lane & 7) + ((lane >> 3) & 1)*8;
    const int b_nc  = (lane >> 4)*8;

    kb_prefetch(smb, AgH, AgL, BgH, BgL, 0, tid);
    cp_commit();

    for (int ch = 0; ch < 6; ch++) {
        if (ch + 1 < 6) {
            kb_prefetch(smb + ((ch+1)&1)*KB_STG, AgH, AgL, BgH, BgL, (ch+1)*64, tid);
            cp_commit();
            cp_wait<1>();
        } else {
            cp_wait<0>();
        }
        __syncthreads();

        const __nv_bfloat16* aH = smb + (ch&1)*KB_STG;
        const __nv_bfloat16* bH = aH + 2*128*APAD;
#pragma unroll
        for (int kk = 0; kk < 64; kk += 16) {
            unsigned aHf[4], aLf[4];
            const __nv_bfloat16* pa = aH + (wm + a_row)*APAD + kk + a_kh;
            ldmx4(aHf, smem_u32(pa));
            ldmx4(aLf, smem_u32(pa + 128*APAD));
#pragma unroll
            for (int nh = 0; nh < 4; nh++) {
                const __nv_bfloat16* pb = bH + (kk + b_kr)*BPAD + wn + nh*16 + b_nc;
                unsigned bHf[4], bLf[4];
                ldmx4t(bHf, smem_u32(pb));
                ldmx4t(bLf, smem_u32(pb + 64*BPAD));
#pragma unroll
                for (int sub = 0; sub < 2; sub++) {
                    int nj = nh*2 + sub;
                    mma16816(acc[nj], aHf, bHf[sub*2], bHf[sub*2+1]);
                    mma16816(acc[nj], aHf, bLf[sub*2], bLf[sub*2+1]);
                    mma16816(acc[nj], aLf, bHf[sub*2], bHf[sub*2+1]);
                }
            }
        }
        __syncthreads();
    }

    float* __restrict__ Od = g_outm + (size_t)h*MTOT;
    int r0 = I0 + wm + (lane >> 2);
#pragma unroll
    for (int nj = 0; nj < 8; nj++) {
        int c = J0 + wn + nj*8 + (lane & 3)*2;
        *reinterpret_cast<float2*>(Od + (size_t)r0*NN + c) =
            make_float2(acc[nj][0], acc[nj][1]);
        *reinterpret_cast<float2*>(Od + (size_t)(r0+8)*NN + c) =
            make_float2(acc[nj][2], acc[nj][3]);
    }
}

// ---------------- kernel C: gate*out @ Wo + bo + residual + LN -----------------
__global__ void __launch_bounds__(T, 1)
kernelC(const float* __restrict__ pair,
        const float* __restrict__ bo,
        const float* __restrict__ ng,
        const float* __restrict__ nb,
        float* __restrict__ out)
{
    extern __shared__ __align__(16) char smC[];
    __nv_bfloat16* vH = (__nv_bfloat16*)smC;                // [128][XPAD]
    __nv_bfloat16* vL = vH + 128*XPAD;
    __nv_bfloat16* wst = vL + 128*XPAD;
    float* y_s  = (float*)(smC + 139264);                   // [128][129]
    float* mu_s = (float*)(smC + 205312);
    float* rs_s = mu_s + 128;

    const int tid = threadIdx.x;
    const int lane = tid & 31, wid = tid >> 5;
    const int wm = (wid & 7)*16, wn = (wid >> 3)*64;
    const int a_row = (lane & 7) + ((lane >> 3) & 1)*8;
    const int a_kh  = (lane >> 4)*8;
    const int b_kr  = (lane & 7) + ((lane >> 3) & 1)*8;
    const int b_nc  = (lane >> 4)*8;
    const size_t IJ0 = (size_t)blockIdx.x * 128;

    // v = out*gate -> y_s (transposed staging), coalesced channel-major reads
    for (int i = tid; i < 128*128; i += T) {
        int h = i >> 7, r = i & 127;
        size_t g = (size_t)h * MTOT + IJ0 + r;
        y_s[r*129 + h] = g_outm[g] * g_gate[g];
    }
    __syncthreads();
    // split to bf16 planes
    for (int i = tid; i < 128*64; i += T) {
        int r = i >> 6, c2 = i & 63;
        unsigned hw, lw;
        split2(y_s[r*129 + 2*c2], y_s[r*129 + 2*c2 + 1], hw, lw);
        *reinterpret_cast<unsigned*>(vH + r*XPAD + 2*c2) = hw;
        *reinterpret_cast<unsigned*>(vL + r*XPAD + 2*c2) = lw;
    }

    float acc[8][4];
    hmma_proj(vH, vL, g_WoH, g_WoL, wst, acc, tid, wm, wn, a_row, a_kh, b_kr, b_nc);

    // y = acc + bo + pair residual -> y_s
    {
        int r = wm + (lane >> 2);
#pragma unroll
        for (int nj = 0; nj < 8; nj++) {
            int c = wn + nj*8 + (lane & 3)*2;
            float b0 = __ldg(bo + c), b1 = __ldg(bo + c + 1);
            float2 p0 = *reinterpret_cast<const float2*>(pair + (IJ0 + r)*CC + c);
            float2 p1 = *reinterpret_cast<const float2*>(pair + (IJ0 + r + 8)*CC + c);
            y_s[r*129 + c]       = acc[nj][0] + b0 + p0.x;
            y_s[r*129 + c+1]     = acc[nj][1] + b1 + p0.y;
            y_s[(r+8)*129 + c]   = acc[nj][2] + b0 + p1.x;
            y_s[(r+8)*129 + c+1] = acc[nj][3] + b1 + p1.y;
        }
    }
    __syncthreads();

    // row LN: warp per 8 rows via shuffle — SCALAR smem loads
    // (row stride 129 floats = 516 B is NOT 16B-aligned; float4 here faulted in R6)
#pragma unroll
    for (int rr = 0; rr < 8; rr++) {
        int r = wid*8 + rr;
        const float* row = y_s + r*129 + lane*4;
        float v0 = row[0], v1 = row[1], v2 = row[2], v3 = row[3];
        float s  = v0 + v1 + v2 + v3;
        float s2 = v0*v0 + v1*v1 + v2*v2 + v3*v3;
#pragma unroll
        for (int off = 16; off > 0; off >>= 1) {
            s  += __shfl_xor_sync(0xffffffffu, s,  off);
            s2 += __shfl_xor_sync(0xffffffffu, s2, off);
        }
        if (lane == 0) {
            float mu  = s * (1.f/128.f);
            float var = fmaxf(s2 * (1.f/128.f) - mu*mu, 0.f) + EPS;
            mu_s[r] = mu;
            rs_s[r] = rsqrtf(var);
        }
    }
    __syncthreads();

    for (int i = tid; i < 128*128; i += T) {
        int r = i >> 7, c = i & 127;
        float z = y_s[r*129 + c];
        out[(IJ0 + r)*CC + c] = (z - mu_s[r]) * rs_s[r] * __ldg(ng + c) + __ldg(nb + c);
    }
}

// ---------------- launch --------------------------------------------------------
extern "C" void kernel_launch(void* const* d_in, const int* in_sizes, int n_in,
                              void* d_out, int out_size)
{
    const float* pair   = (const float*)d_in[0];
    const float* ln_l_g = (const float*)d_in[1];
    const float* ln_l_b = (const float*)d_in[2];
    const float* ln_r_g = (const float*)d_in[3];
    const float* ln_r_b = (const float*)d_in[4];
    const float* Wl     = (const float*)d_in[5];
    const float* bl     = (const float*)d_in[6];
    const float* Wr     = (const float*)d_in[7];
    const float* br     = (const float*)d_in[8];
    const float* Wg     = (const float*)d_in[9];
    const float* bg     = (const float*)d_in[10];
    const float* Wo     = (const float*)d_in[11];
    const float* bo     = (const float*)d_in[12];
    const float* n_g    = (const float*)d_in[13];
    const float* n_b    = (const float*)d_in[14];
    float* out = (float*)d_out;

    static __nv_bfloat16 *pWlH = nullptr, *pWlL, *pWrH, *pWrL, *pWgH, *pWgL, *pWoH, *pWoL;
    static float *pbLE, *pbRE, *pWgS;
    if (!pWlH) {
        cudaGetSymbolAddress((void**)&pWlH, g_WlH);
        cudaGetSymbolAddress((void**)&pWlL, g_WlL);
        cudaGetSymbolAddress((void**)&pWrH, g_WrH);
        cudaGetSymbolAddress((void**)&pWrL, g_WrL);
        cudaGetSymbolAddress((void**)&pWgH, g_WgH);
        cudaGetSymbolAddress((void**)&pWgL, g_WgL);
        cudaGetSymbolAddress((void**)&pWoH, g_WoH);
        cudaGetSymbolAddress((void**)&pWoL, g_WoL);
        cudaGetSymbolAddress((void**)&pbLE, g_bLE);
        cudaGetSymbolAddress((void**)&pbRE, g_bRE);
        cudaGetSymbolAddress((void**)&pWgS, g_WgS);
    }

    // smem: planes 69632 | wst 69632 | stage 66048 | stats
    const size_t smemA = 206848;
    const size_t smemC = 206336;
    const size_t smemB = (size_t)2*KB_STG*sizeof(__nv_bfloat16);   // 143360
    cudaFuncSetAttribute(kernelA,     cudaFuncAttributeMaxDynamicSharedMemorySize, (int)smemA);
    cudaFuncSetAttribute(kernelC,     cudaFuncAttributeMaxDynamicSharedMemorySize, (int)smemC);
    cudaFuncSetAttribute(kernelB_mma, cudaFuncAttributeMaxDynamicSharedMemorySize, (int)smemB);

    prep_fold<<<CC, CC>>>(Wl, ln_l_g, ln_l_b, bl, pWlH, pWlL, pbLE);
    prep_fold<<<CC, CC>>>(Wr, ln_r_g, ln_r_b, br, pWrH, pWrL, pbRE);
    prep_pack<<<CC, CC>>>(Wg, pWgH, pWgL, pWgS);
    prep_pack<<<CC, CC>>>(Wo, pWoH, pWoL, nullptr);

    kernelA<<<MTOT/128, T, smemA>>>(pair, bg);
    kernelB_mma<<<dim3(NN/128, NN/128, CC), T, smemB>>>();
    kernelC<<<MTOT/128, T, smemC>>>(pair, bo, n_g, n_b, out);
}

// round 8
// speedup vs baseline: 2.5068x; 1.1899x over previous
#include <cuda_runtime.h>
#include <cuda_fp16.h>
#include <math.h>

// Problem constants (fixed by dataset): B=1, N=384, C=H=128
#define NN   384
#define CC   128
#define MTOT (NN*NN)
#define EPS  1e-5f
#define XPAD 136      // data plane row stride (fp16 elems)
#define BPAD 136      // weight / right row stride (fp16 elems)
#define APAD 72       // kernelB left-tile row stride (fp16 elems)
#define T    512      // threads per block (16 warps)

// ---------------- scratch ------------------------------------------------------
// Split-fp16: H = fp16(x), L = fp16(x - H)  (x = H + L exact to ~2^-22).
// Per GEMM only one operand is split (2 MMAs); the other is single fp16,
// whose 2^-12 rounding dominates the error (~3e-5 rel, 30x under tolerance).
__device__ __half g_leftH [(size_t)CC * MTOT];   // [h][i][k]
__device__ __half g_leftL [(size_t)CC * MTOT];
__device__ __half g_rightH[(size_t)CC * MTOT];   // [h][k][j]  (single plane)
__device__ float g_gate[(size_t)CC * MTOT];      // [h][i*N+j]
__device__ float g_outm[(size_t)CC * MTOT];      // [h][i*N+j]
__device__ __half g_WlH[CC*CC], g_WlL[CC*CC];    // LN-folded split weights [k][n]
__device__ __half g_WrH[CC*CC], g_WrL[CC*CC];
__device__ __half g_WgH[CC*CC], g_WgL[CC*CC];
__device__ __half g_WoH[CC*CC], g_WoL[CC*CC];
__device__ float g_bLE[CC], g_bRE[CC], g_WgS[CC];

// ---------------- helpers (baseline PTX only) ----------------------------------
__device__ __forceinline__ unsigned smem_u32(const void* p) {
    return (unsigned)__cvta_generic_to_shared(p);
}
__device__ __forceinline__ void cp16(unsigned saddr, const void* g) {
    asm volatile("cp.async.cg.shared.global [%0], [%1], 16;" :: "r"(saddr), "l"(g));
}
__device__ __forceinline__ void cp_commit() {
    asm volatile("cp.async.commit_group;" ::: "memory");
}
template<int N>
__device__ __forceinline__ void cp_wait() {
    asm volatile("cp.async.wait_group %0;" :: "n"(N) : "memory");
}
__device__ __forceinline__ void ldmx4(unsigned r[4], unsigned addr) {
    asm volatile("ldmatrix.sync.aligned.m8n8.x4.shared.b16 {%0,%1,%2,%3}, [%4];"
        : "=r"(r[0]), "=r"(r[1]), "=r"(r[2]), "=r"(r[3]) : "r"(addr));
}
__device__ __forceinline__ void ldmx4t(unsigned r[4], unsigned addr) {
    asm volatile("ldmatrix.sync.aligned.m8n8.x4.trans.shared.b16 {%0,%1,%2,%3}, [%4];"
        : "=r"(r[0]), "=r"(r[1]), "=r"(r[2]), "=r"(r[3]) : "r"(addr));
}
__device__ __forceinline__ void mma16816(float d[4], const unsigned a[4],
                                         unsigned b0, unsigned b1) {
    asm volatile(
        "mma.sync.aligned.m16n8k16.row.col.f32.f16.f16.f32 "
        "{%0,%1,%2,%3}, {%4,%5,%6,%7}, {%8,%9}, {%0,%1,%2,%3};"
        : "+f"(d[0]), "+f"(d[1]), "+f"(d[2]), "+f"(d[3])
        : "r"(a[0]), "r"(a[1]), "r"(a[2]), "r"(a[3]), "r"(b0), "r"(b1));
}
__device__ __forceinline__ unsigned pack_splitH(float v) {   // hi<<16 | lo (fp16)
    __half hi = __float2half_rn(v);
    float r = v - __half2float(hi);
    __half lo = __float2half_rn(r);
    return ((unsigned)__half_as_ushort(hi) << 16) | (unsigned)__half_as_ushort(lo);
}

// ---------------- prep kernels --------------------------------------------------
__global__ void prep_fold(const float* __restrict__ W,
                          const float* __restrict__ g,
                          const float* __restrict__ beta,
                          const float* __restrict__ b,
                          __half* __restrict__ WH,
                          __half* __restrict__ WL,
                          float* __restrict__ bE)
{
    int k = blockIdx.x, n = threadIdx.x;
    float v = g[k] * W[k*CC + n];
    __half hi = __float2half_rn(v);
    WH[k*CC + n] = hi;
    WL[k*CC + n] = __float2half_rn(v - __half2float(hi));
    if (k == 0) {
        float s = b[n];
        for (int kk = 0; kk < CC; kk++) s += beta[kk] * W[kk*CC + n];
        bE[n] = s;
    }
}
__global__ void prep_pack(const float* __restrict__ W,
                          __half* __restrict__ WH,
                          __half* __restrict__ WL,
                          float* __restrict__ S)
{
    int k = blockIdx.x, n = threadIdx.x;
    float v = W[k*CC + n];
    __half hi = __float2half_rn(v);
    WH[k*CC + n] = hi;
    WL[k*CC + n] = __float2half_rn(v - __half2float(hi));
    if (k == 0 && S) {
        float s = 0.f;
        for (int kk = 0; kk < CC; kk++) s += W[kk*CC + n];
        S[n] = s;
    }
}

// ---------------- HMMA projection GEMM: xhat(single) x W(split), 2 MMAs --------
// A: single fp16 plane [128][XPAD]; weights: 2-plane split streamed 2-stage.
__device__ __forceinline__ void hmma_proj(
    const __half* __restrict__ aP,
    const __half* __restrict__ WH,
    const __half* __restrict__ WL,
    __half* __restrict__ wst,
    float acc[8][4],
    int tid, int wm, int wn,
    int a_row, int a_kh, int b_kr, int b_nc)
{
    const int PLANE = 64*BPAD;
#pragma unroll
    for (int nj = 0; nj < 8; nj++)
#pragma unroll
        for (int q = 0; q < 4; q++) acc[nj][q] = 0.f;

#pragma unroll
    for (int s = 0; s < 2; s++) {
        __half* dH = wst + s*2*PLANE;
        __half* dL = dH + PLANE;
        int k0 = s*64;
#pragma unroll
        for (int t = 0; t < 4; t++) {
            int idx = tid + t*T;            // 0..2047
            int r = idx >> 5, rem = idx & 31;
            int pl = rem >> 4, c = rem & 15;
            const __half* src = (pl ? WL : WH) + (k0 + r)*CC + c*8;
            __half* dst = (pl ? dL : dH) + r*BPAD + c*8;
            cp16(smem_u32(dst), src);
        }
        cp_commit();
    }

#pragma unroll
    for (int s = 0; s < 2; s++) {
        if (s == 0) cp_wait<1>(); else cp_wait<0>();
        __syncthreads();
        const __half* bH = wst + s*2*PLANE;
        int k0 = s*64;
#pragma unroll
        for (int kk = 0; kk < 64; kk += 16) {
            unsigned aF[4];
            ldmx4(aF, smem_u32(aP + (wm + a_row)*XPAD + k0 + kk + a_kh));
#pragma unroll
            for (int nh = 0; nh < 4; nh++) {
                const __half* pb = bH + (kk + b_kr)*BPAD + wn + nh*16 + b_nc;
                unsigned bHf[4], bLf[4];
                ldmx4t(bHf, smem_u32(pb));
                ldmx4t(bLf, smem_u32(pb + PLANE));
#pragma unroll
                for (int sub = 0; sub < 2; sub++) {
                    int nj = nh*2 + sub;
                    mma16816(acc[nj], aF, bHf[sub*2], bHf[sub*2+1]);
                    mma16816(acc[nj], aF, bLf[sub*2], bLf[sub*2+1]);
                }
            }
        }
    }
    __syncthreads();   // protect wst for next call
}

// fragment -> transposed channel-major global, split H/L fp16 planes (left)
__device__ __forceinline__ void frag_store_pack(
    const float acc[8][4], const float* __restrict__ bias,
    unsigned* __restrict__ stage,
    __half* __restrict__ dstH, __half* __restrict__ dstL,
    size_t R0, int lane, int wm, int wn, int tid)
{
    int r = wm + (lane >> 2);
#pragma unroll
    for (int nj = 0; nj < 8; nj++) {
        int c = wn + nj*8 + (lane & 3)*2;
        float b0 = __ldg(bias + c), b1 = __ldg(bias + c + 1);
        stage[c*129 + r]       = pack_splitH(acc[nj][0] + b0);
        stage[(c+1)*129 + r]   = pack_splitH(acc[nj][1] + b1);
        stage[c*129 + r+8]     = pack_splitH(acc[nj][2] + b0);
        stage[(c+1)*129 + r+8] = pack_splitH(acc[nj][3] + b1);
    }
    __syncthreads();
    for (int idx = tid; idx < 128*64; idx += T) {
        int n = idx >> 6, r2 = idx & 63;
        unsigned w0 = stage[n*129 + 2*r2], w1 = stage[n*129 + 2*r2 + 1];
        unsigned hw = (w0 >> 16) | (w1 & 0xFFFF0000u);
        unsigned lw = (w0 & 0xFFFFu) | (w1 << 16);
        size_t base = (size_t)n*MTOT + R0 + 2*r2;
        *reinterpret_cast<unsigned*>(dstH + base) = hw;
        *reinterpret_cast<unsigned*>(dstL + base) = lw;
    }
    __syncthreads();
}

// fragment -> transposed channel-major, SINGLE fp16 plane (right)
__device__ __forceinline__ void frag_store_single(
    const float acc[8][4], const float* __restrict__ bias,
    unsigned* __restrict__ stage,
    __half* __restrict__ dstH,
    size_t R0, int lane, int wm, int wn, int tid)
{
    int r = wm + (lane >> 2);
#pragma unroll
    for (int nj = 0; nj < 8; nj++) {
        int c = wn + nj*8 + (lane & 3)*2;
        float b0 = __ldg(bias + c), b1 = __ldg(bias + c + 1);
        stage[c*129 + r]       = (unsigned)__half_as_ushort(__float2half_rn(acc[nj][0] + b0));
        stage[(c+1)*129 + r]   = (unsigned)__half_as_ushort(__float2half_rn(acc[nj][1] + b1));
        stage[c*129 + r+8]     = (unsigned)__half_as_ushort(__float2half_rn(acc[nj][2] + b0));
        stage[(c+1)*129 + r+8] = (unsigned)__half_as_ushort(__float2half_rn(acc[nj][3] + b1));
    }
    __syncthreads();
    for (int idx = tid; idx < 128*64; idx += T) {
        int n = idx >> 6, r2 = idx & 63;
        unsigned w0 = stage[n*129 + 2*r2], w1 = stage[n*129 + 2*r2 + 1];
        unsigned hw = (w0 & 0xFFFFu) | (w1 << 16);
        size_t base = (size_t)n*MTOT + R0 + 2*r2;
        *reinterpret_cast<unsigned*>(dstH + base) = hw;
    }
    __syncthreads();
}

// gate: logit = sd[r]*acc + mu[r]*S[c] + bg[c]; sigmoid; fp32 channel-major
__device__ __forceinline__ void frag_store_gate(
    const float acc[8][4], const float* __restrict__ bg,
    const float* __restrict__ Sg,
    const float* __restrict__ sd_s, const float* __restrict__ mu_s,
    float* __restrict__ stage, float* __restrict__ dst,
    size_t R0, int lane, int wm, int wn, int tid)
{
    int r = wm + (lane >> 2);
    float sd0 = sd_s[r], mu0 = mu_s[r];
    float sd1 = sd_s[r+8], mu1 = mu_s[r+8];
#pragma unroll
    for (int nj = 0; nj < 8; nj++) {
        int c = wn + nj*8 + (lane & 3)*2;
        float S0 = __ldg(Sg + c) , B0 = __ldg(bg + c);
        float S1 = __ldg(Sg + c+1), B1 = __ldg(bg + c+1);
        float z;
        z = sd0*acc[nj][0] + mu0*S0 + B0; stage[c*129 + r]       = 1.f/(1.f+expf(-z));
        z = sd0*acc[nj][1] + mu0*S1 + B1; stage[(c+1)*129 + r]   = 1.f/(1.f+expf(-z));
        z = sd1*acc[nj][2] + mu1*S0 + B0; stage[c*129 + r+8]     = 1.f/(1.f+expf(-z));
        z = sd1*acc[nj][3] + mu1*S1 + B1; stage[(c+1)*129 + r+8] = 1.f/(1.f+expf(-z));
    }
    __syncthreads();
    for (int idx = tid; idx < 128*128; idx += T) {
        int n = idx >> 7, r2 = idx & 127;
        dst[(size_t)n * MTOT + R0 + r2] = stage[n*129 + r2];
    }
    __syncthreads();
}

// ---------------- kernel A: LN + 3 projections ---------------------------------
__global__ void __launch_bounds__(T, 1)
kernelA(const float* __restrict__ pair,
        const float* __restrict__ bg)
{
    extern __shared__ __align__(16) char smA[];
    __half* xh  = (__half*)smA;                    // [128][XPAD] single plane (34816 B)
    __half* wst = xh + 128*XPAD;                   // 2 stages x 2 planes x 64*BPAD (69632 B)
    char* stg = smA + 104448;                      // [128][129] u32/f32 stage (66048 B)
    unsigned* stageU = (unsigned*)stg;
    float*    stageF = (float*)stg;
    float* mu_s = (float*)(smA + 170496);
    float* rs_s = mu_s + 128;
    float* sd_s = rs_s + 128;

    const int tid = threadIdx.x;
    const int lane = tid & 31, wid = tid >> 5;
    const int wm = (wid & 7)*16, wn = (wid >> 3)*64;
    const int a_row = (lane & 7) + ((lane >> 3) & 1)*8;
    const int a_kh  = (lane >> 4)*8;
    const int b_kr  = (lane & 7) + ((lane >> 3) & 1)*8;
    const int b_nc  = (lane >> 4)*8;
    const size_t R0 = (size_t)blockIdx.x * 128;

    // LN stats: warp per 8 rows, coalesced global float4 read + shuffle reduce
#pragma unroll
    for (int rr = 0; rr < 8; rr++) {
        int r = wid*8 + rr;
        float4 v = *reinterpret_cast<const float4*>(pair + (R0 + r)*CC + lane*4);
        float s  = v.x + v.y + v.z + v.w;
        float s2 = v.x*v.x + v.y*v.y + v.z*v.z + v.w*v.w;
#pragma unroll
        for (int off = 16; off > 0; off >>= 1) {
            s  += __shfl_xor_sync(0xffffffffu, s,  off);
            s2 += __shfl_xor_sync(0xffffffffu, s2, off);
        }
        if (lane == 0) {
            float mu  = s * (1.f/128.f);
            float var = fmaxf(s2 * (1.f/128.f) - mu*mu, 0.f) + EPS;
            mu_s[r] = mu;
            rs_s[r] = rsqrtf(var);
            sd_s[r] = sqrtf(var);
        }
    }
    __syncthreads();

    // xhat -> single fp16 plane (pair re-read is L2-hot)
    for (int i = tid; i < 128*32; i += T) {
        int r = i >> 5, c4 = i & 31;
        float4 v = *reinterpret_cast<const float4*>(pair + (R0 + r)*CC + c4*4);
        float mu = mu_s[r], rs = rs_s[r];
        __half2 h0 = __floats2half2_rn((v.x - mu)*rs, (v.y - mu)*rs);
        __half2 h1 = __floats2half2_rn((v.z - mu)*rs, (v.w - mu)*rs);
        *reinterpret_cast<uint2*>(xh + r*XPAD + c4*4) =
            make_uint2(*(unsigned*)&h0, *(unsigned*)&h1);
    }
    // hmma_proj's internal sync (post cp_wait) orders plane writes before ldmatrix

    float acc[8][4];
    hmma_proj(xh, g_WlH, g_WlL, wst, acc, tid, wm, wn, a_row, a_kh, b_kr, b_nc);
    frag_store_pack(acc, g_bLE, stageU, g_leftH, g_leftL, R0, lane, wm, wn, tid);
    hmma_proj(xh, g_WrH, g_WrL, wst, acc, tid, wm, wn, a_row, a_kh, b_kr, b_nc);
    frag_store_single(acc, g_bRE, stageU, g_rightH, R0, lane, wm, wn, tid);
    hmma_proj(xh, g_WgH, g_WgL, wst, acc, tid, wm, wn, a_row, a_kh, b_kr, b_nc);
    frag_store_gate(acc, bg, g_WgS, sd_s, mu_s, stageF, g_gate, R0, lane, wm, wn, tid);
}

// ---------------- kernel B: per-channel 384^3 GEMM, left split x right single --
#define KB_STG (2*128*APAD + 64*BPAD)   // fp16 elements per stage (27136)

__device__ __forceinline__ void kb_prefetch(
    __half* st,
    const __half* __restrict__ AgH, const __half* __restrict__ AgL,
    const __half* __restrict__ BgH,
    int k0, int tid)
{
    __half* aH = st;
    __half* aL = st + 128*APAD;
    __half* bH = st + 2*128*APAD;
#pragma unroll
    for (int t = 0; t < 4; t++) {
        int idx = tid + t*T;                // 0..2047
        int r = idx >> 4, rem = idx & 15;
        int pl = rem >> 3, c = rem & 7;
        const __half* src = (pl ? AgL : AgH) + (size_t)r*NN + k0 + c*8;
        __half* dst = (pl ? aL : aH) + r*APAD + c*8;
        cp16(smem_u32(dst), src);
    }
#pragma unroll
    for (int t = 0; t < 2; t++) {
        int idx = tid + t*T;                // 0..1023
        int r = idx >> 4, c = idx & 15;     // 64 rows x 128 cols
        const __half* src = BgH + (size_t)(k0 + r)*NN + c*8;
        __half* dst = bH + r*BPAD + c*8;
        cp16(smem_u32(dst), src);
    }
}

__global__ void __launch_bounds__(T, 1)
kernelB_mma()
{
    extern __shared__ __align__(16) __half smb[];
    const int tid  = threadIdx.x;
    const int lane = tid & 31, wid = tid >> 5;
    const int J0 = blockIdx.x*128, I0 = blockIdx.y*128, h = blockIdx.z;
    const int wm = (wid & 7)*16, wn = (wid >> 3)*64;

    const __half* __restrict__ AgH = g_leftH  + (size_t)h*MTOT + (size_t)I0*NN;
    const __half* __restrict__ AgL = g_leftL  + (size_t)h*MTOT + (size_t)I0*NN;
    const __half* __restrict__ BgH = g_rightH + (size_t)h*MTOT + J0;

    float acc[8][4];
#pragma unroll
    for (int nj = 0; nj < 8; nj++)
#pragma unroll
        for (int q = 0; q < 4; q++) acc[nj][q] = 0.f;

    const int a_row = (lane & 7) + ((lane >> 3) & 1)*8;
    const int a_kh  = (lane >> 4)*8;
    const int b_kr  = (lane & 7) + ((lane >> 3) & 1)*8;
    const int b_nc  = (lane >> 4)*8;

    kb_prefetch(smb, AgH, AgL, BgH, 0, tid);
    cp_commit();

    for (int ch = 0; ch < 6; ch++) {
        if (ch + 1 < 6) {
            kb_prefetch(smb + ((ch+1)&1)*KB_STG, AgH, AgL, BgH, (ch+1)*64, tid);
            cp_commit();
            cp_wait<1>();
        } else {
            cp_wait<0>();
        }
        __syncthreads();

        const __half* aH = smb + (ch&1)*KB_STG;
        const __half* bH = aH + 2*128*APAD;
#pragma unroll
        for (int kk = 0; kk < 64; kk += 16) {
            unsigned lHf[4], lLf[4];
            const __half* pa = aH + (wm + a_row)*APAD + kk + a_kh;
            ldmx4(lHf, smem_u32(pa));
            ldmx4(lLf, smem_u32(pa + 128*APAD));
#pragma unroll
            for (int nh = 0; nh < 4; nh++) {
                unsigned rHf[4];
                ldmx4t(rHf, smem_u32(bH + (kk + b_kr)*BPAD + wn + nh*16 + b_nc));
#pragma unroll
                for (int sub = 0; sub < 2; sub++) {
                    int nj = nh*2 + sub;
                    mma16816(acc[nj], lHf, rHf[sub*2], rHf[sub*2+1]);
                    mma16816(acc[nj], lLf, rHf[sub*2], rHf[sub*2+1]);
                }
            }
        }
        __syncthreads();
    }

    float* __restrict__ Od = g_outm + (size_t)h*MTOT;
    int r0 = I0 + wm + (lane >> 2);
#pragma unroll
    for (int nj = 0; nj < 8; nj++) {
        int c = J0 + wn + nj*8 + (lane & 3)*2;
        *reinterpret_cast<float2*>(Od + (size_t)r0*NN + c) =
            make_float2(acc[nj][0], acc[nj][1]);
        *reinterpret_cast<float2*>(Od + (size_t)(r0+8)*NN + c) =
            make_float2(acc[nj][2], acc[nj][3]);
    }
}

// ---------------- kernel C: gate*out @ Wo + bo + residual + LN -----------------
__global__ void __launch_bounds__(T, 1)
kernelC(const float* __restrict__ pair,
        const float* __restrict__ bo,
        const float* __restrict__ ng,
        const float* __restrict__ nb,
        float* __restrict__ out)
{
    extern __shared__ __align__(16) char smC[];
    __half* vP  = (__half*)smC;                    // [128][XPAD] single plane
    __half* wst = vP + 128*XPAD;                   // weight stages
    float* y_s  = (float*)(smC + 104448);          // [128][129]
    float* mu_s = (float*)(smC + 170496);
    float* rs_s = mu_s + 128;

    const int tid = threadIdx.x;
    const int lane = tid & 31, wid = tid >> 5;
    const int wm = (wid & 7)*16, wn = (wid >> 3)*64;
    const int a_row = (lane & 7) + ((lane >> 3) & 1)*8;
    const int a_kh  = (lane >> 4)*8;
    const int b_kr  = (lane & 7) + ((lane >> 3) & 1)*8;
    const int b_nc  = (lane >> 4)*8;
    const size_t IJ0 = (size_t)blockIdx.x * 128;

    // v = out*gate -> y_s (transposed staging), coalesced channel-major reads
    for (int i = tid; i < 128*128; i += T) {
        int h = i >> 7, r = i & 127;
        size_t g = (size_t)h * MTOT + IJ0 + r;
        y_s[r*129 + h] = g_outm[g] * g_gate[g];
    }
    __syncthreads();
    // v -> single fp16 plane
    for (int i = tid; i < 128*64; i += T) {
        int r = i >> 6, c2 = i & 63;
        __half2 h2 = __floats2half2_rn(y_s[r*129 + 2*c2], y_s[r*129 + 2*c2 + 1]);
        *reinterpret_cast<unsigned*>(vP + r*XPAD + 2*c2) = *(unsigned*)&h2;
    }

    float acc[8][4];
    hmma_proj(vP, g_WoH, g_WoL, wst, acc, tid, wm, wn, a_row, a_kh, b_kr, b_nc);

    // y = acc + bo + pair residual -> y_s
    {
        int r = wm + (lane >> 2);
#pragma unroll
        for (int nj = 0; nj < 8; nj++) {
            int c = wn + nj*8 + (lane & 3)*2;
            float b0 = __ldg(bo + c), b1 = __ldg(bo + c + 1);
            float2 p0 = *reinterpret_cast<const float2*>(pair + (IJ0 + r)*CC + c);
            float2 p1 = *reinterpret_cast<const float2*>(pair + (IJ0 + r + 8)*CC + c);
            y_s[r*129 + c]       = acc[nj][0] + b0 + p0.x;
            y_s[r*129 + c+1]     = acc[nj][1] + b1 + p0.y;
            y_s[(r+8)*129 + c]   = acc[nj][2] + b0 + p1.x;
            y_s[(r+8)*129 + c+1] = acc[nj][3] + b1 + p1.y;
        }
    }
    __syncthreads();

    // row LN: warp per 8 rows via shuffle — SCALAR smem loads (516B row stride)
#pragma unroll
    for (int rr = 0; rr < 8; rr++) {
        int r = wid*8 + rr;
        const float* row = y_s + r*129 + lane*4;
        float v0 = row[0], v1 = row[1], v2 = row[2], v3 = row[3];
        float s  = v0 + v1 + v2 + v3;
        float s2 = v0*v0 + v1*v1 + v2*v2 + v3*v3;
#pragma unroll
        for (int off = 16; off > 0; off >>= 1) {
            s  += __shfl_xor_sync(0xffffffffu, s,  off);
            s2 += __shfl_xor_sync(0xffffffffu, s2, off);
        }
        if (lane == 0) {
            float mu  = s * (1.f/128.f);
            float var = fmaxf(s2 * (1.f/128.f) - mu*mu, 0.f) + EPS;
            mu_s[r] = mu;
            rs_s[r] = rsqrtf(var);
        }
    }
    __syncthreads();

    for (int i = tid; i < 128*128; i += T) {
        int r = i >> 7, c = i & 127;
        float z = y_s[r*129 + c];
        out[(IJ0 + r)*CC + c] = (z - mu_s[r]) * rs_s[r] * __ldg(ng + c) + __ldg(nb + c);
    }
}

// ---------------- launch --------------------------------------------------------
extern "C" void kernel_launch(void* const* d_in, const int* in_sizes, int n_in,
                              void* d_out, int out_size)
{
    const float* pair   = (const float*)d_in[0];
    const float* ln_l_g = (const float*)d_in[1];
    const float* ln_l_b = (const float*)d_in[2];
    const float* ln_r_g = (const float*)d_in[3];
    const float* ln_r_b = (const float*)d_in[4];
    const float* Wl     = (const float*)d_in[5];
    const float* bl     = (const float*)d_in[6];
    const float* Wr     = (const float*)d_in[7];
    const float* br     = (const float*)d_in[8];
    const float* Wg     = (const float*)d_in[9];
    const float* bg     = (const float*)d_in[10];
    const float* Wo     = (const float*)d_in[11];
    const float* bo     = (const float*)d_in[12];
    const float* n_g    = (const float*)d_in[13];
    const float* n_b    = (const float*)d_in[14];
    float* out = (float*)d_out;

    static __half *pWlH = nullptr, *pWlL, *pWrH, *pWrL, *pWgH, *pWgL, *pWoH, *pWoL;
    static float *pbLE, *pbRE, *pWgS;
    if (!pWlH) {
        cudaGetSymbolAddress((void**)&pWlH, g_WlH);
        cudaGetSymbolAddress((void**)&pWlL, g_WlL);
        cudaGetSymbolAddress((void**)&pWrH, g_WrH);
        cudaGetSymbolAddress((void**)&pWrL, g_WrL);
        cudaGetSymbolAddress((void**)&pWgH, g_WgH);
        cudaGetSymbolAddress((void**)&pWgL, g_WgL);
        cudaGetSymbolAddress((void**)&pWoH, g_WoH);
        cudaGetSymbolAddress((void**)&pWoL, g_WoL);
        cudaGetSymbolAddress((void**)&pbLE, g_bLE);
        cudaGetSymbolAddress((void**)&pbRE, g_bRE);
        cudaGetSymbolAddress((void**)&pWgS, g_WgS);
    }

    // smem: plane 34816 | wst 69632 | stage 66048 | stats
    const size_t smemA = 172032;
    const size_t smemC = 172032;
    const size_t smemB = (size_t)2*KB_STG*sizeof(__half);   // 108544
    cudaFuncSetAttribute(kernelA,     cudaFuncAttributeMaxDynamicSharedMemorySize, (int)smemA);
    cudaFuncSetAttribute(kernelC,     cudaFuncAttributeMaxDynamicSharedMemorySize, (int)smemC);
    cudaFuncSetAttribute(kernelB_mma, cudaFuncAttributeMaxDynamicSharedMemorySize, (int)smemB);

    prep_fold<<<CC, CC>>>(Wl, ln_l_g, ln_l_b, bl, pWlH, pWlL, pbLE);
    prep_fold<<<CC, CC>>>(Wr, ln_r_g, ln_r_b, br, pWrH, pWrL, pbRE);
    prep_pack<<<CC, CC>>>(Wg, pWgH, pWgL, pWgS);
    prep_pack<<<CC, CC>>>(Wo, pWoH, pWoL, nullptr);

    kernelA<<<MTOT/128, T, smemA>>>(pair, bg);
    kernelB_mma<<<dim3(NN/128, NN/128, CC), T, smemB>>>();
    kernelC<<<MTOT/128, T, smemC>>>(pair, bo, n_g, n_b, out);
}